// round 10
// baseline (speedup 1.0000x reference)
#include <cuda_runtime.h>

// Problem constants
#define B_    8
#define S_    1024
#define D_    768
#define H_    12
#define DK_   64
#define MROWS 8192                    // B*S
#define BSD   6291456                 // MROWS*D
#define BHSS  100663296LL             // B*H*S*S

#define NBLK  296                     // 2 per SM x 148 SMs, co-resident
#define NTHR  512
#define DYN_SMEM 72192                // score phase high-water: 18048 floats

// Device-global scratch — used ONLY within a single kernel launch.
__device__ float g_q[BSD];
__device__ float g_k[BSD];
__device__ float g_v[BSD];
__device__ float g_ctx[BSD];
__device__ float g_proj[BSD];
__device__ float g_attn[(size_t)BHSS];   // unnormalized exp(score)
__device__ float g_part[98304 * 8];      // per-row per-jtile partial sums
__device__ float g_inv[98304];           // per-row 1/sum

// Software grid barrier (generation counter; replay-safe).
__device__ unsigned g_bar_count;
__device__ unsigned g_bar_gen;

__device__ __forceinline__ void grid_barrier() {
    __syncthreads();
    if (threadIdx.x == 0) {
        __threadfence();
        unsigned gen = g_bar_gen;
        unsigned old = atomicAdd(&g_bar_count, 1u);
        if (old == (unsigned)(gridDim.x - 1)) {
            g_bar_count = 0;
            __threadfence();
            atomicAdd(&g_bar_gen, 1u);
        } else {
            while (atomicAdd(&g_bar_gen, 0u) == gen) { __nanosleep(64); }
        }
        __threadfence();
    }
    __syncthreads();
}

// cp.async helpers (16B, L2-cached global->shared, register-free)
__device__ __forceinline__ void cpa16(unsigned dst, const float* src) {
    asm volatile("cp.async.cg.shared.global [%0], [%1], 16;"
                 :: "r"(dst), "l"(src));
}
__device__ __forceinline__ void cp_commit() {
    asm volatile("cp.async.commit_group;" ::: "memory");
}
__device__ __forceinline__ void cp_wait1() {
    asm volatile("cp.async.wait_group 1;" ::: "memory");
}
__device__ __forceinline__ void cp_wait0() {
    asm volatile("cp.async.wait_group 0;" ::: "memory");
}

// tf32 mma with raw fp32 bits (HW truncates low 13 mantissa bits).
__device__ __forceinline__ void mma_tf32(float* acc, unsigned a0, unsigned a1,
                                         unsigned a2, unsigned a3,
                                         unsigned b0, unsigned b1) {
    asm volatile(
        "mma.sync.aligned.m16n8k8.row.col.f32.tf32.tf32.f32 "
        "{%0,%1,%2,%3}, {%4,%5,%6,%7}, {%8,%9}, {%0,%1,%2,%3};"
        : "+f"(acc[0]), "+f"(acc[1]), "+f"(acc[2]), "+f"(acc[3])
        : "r"(a0), "r"(a1), "r"(a2), "r"(a3), "r"(b0), "r"(b1));
}
__device__ __forceinline__ unsigned fu(float x) { return __float_as_uint(x); }

// ---------------------------------------------------------------------------
// 128x128 GEMM tile, BK=32, cp.async double-buffered, tf32 mma.
// sA: [m][k] stride 36, 2 bufs @ 0 / 4608.  sB: [k][n] stride 132, 2 bufs
// @ 9216 / 13440.  16 warps (4x4), 32x32 per warp.
// out = A[8192,768] @ W[768,768] + bias.
// ---------------------------------------------------------------------------
__device__ __forceinline__ void gemm_fill(const float* __restrict__ A,
                                          const float* __restrict__ W,
                                          int row0, int col0, int k0,
                                          unsigned sAu, unsigned sBu, int tid) {
    #pragma unroll
    for (int e = 0; e < 2; e++) {
        int idx = e * NTHR + tid;                 // 0..1023
        int m = idx >> 3, c = (idx & 7) * 4;      // A: 8 chunks/row
        cpa16(sAu + (unsigned)(m * 36 + c) * 4,
              &A[(size_t)(row0 + m) * 768 + k0 + c]);
        int k = idx >> 5, c2 = (idx & 31) * 4;    // B: 32 chunks/row
        cpa16(sBu + (unsigned)(k * 132 + c2) * 4,
              &W[(size_t)(k0 + k) * 768 + col0 + c2]);
    }
    cp_commit();
}

__device__ void gemm_tile(const float* __restrict__ A, const float* __restrict__ W,
                          const float* __restrict__ bias, float* __restrict__ out,
                          int tileIdx, float* smem) {
    const int row0 = (tileIdx / 6) * 128;
    const int col0 = (tileIdx % 6) * 128;
    const int tid  = threadIdx.x;
    const int warp = tid >> 5, lane = tid & 31;
    const int gid  = lane >> 2, tig = lane & 3;
    const int wm   = (warp >> 2) * 32, wn = (warp & 3) * 32;

    float* sA = smem;                // 2 x 4608 floats
    float* sB = smem + 9216;         // 2 x 4224 floats
    const unsigned sAu = (unsigned)__cvta_generic_to_shared(sA);
    const unsigned sBu = (unsigned)__cvta_generic_to_shared(sB);

    float acc[2][4][4] = {};

    gemm_fill(A, W, row0, col0, 0, sAu, sBu, tid);
    #pragma unroll 1
    for (int s = 0; s < 24; s++) {
        if (s + 1 < 24) {
            gemm_fill(A, W, row0, col0, (s + 1) * 32,
                      sAu + ((s + 1) & 1) * 4608 * 4,
                      sBu + ((s + 1) & 1) * 4224 * 4, tid);
            cp_wait1();
        } else {
            cp_wait0();
        }
        __syncthreads();
        const float* cA = sA + (s & 1) * 4608;
        const float* cB = sB + (s & 1) * 4224;

        #pragma unroll
        for (int ks = 0; ks < 32; ks += 8) {
            unsigned b0[4], b1[4];
            #pragma unroll
            for (int nt = 0; nt < 4; nt++) {
                const float* bp = &cB[(ks + tig) * 132 + wn + nt * 8 + gid];
                b0[nt] = fu(bp[0]);
                b1[nt] = fu(bp[4 * 132]);
            }
            #pragma unroll
            for (int mt = 0; mt < 2; mt++) {
                const float* ap = &cA[(wm + mt * 16 + gid) * 36 + ks + tig];
                unsigned a0 = fu(ap[0]);
                unsigned a1 = fu(ap[8 * 36]);
                unsigned a2 = fu(ap[4]);
                unsigned a3 = fu(ap[8 * 36 + 4]);
                #pragma unroll
                for (int nt = 0; nt < 4; nt++)
                    mma_tf32(acc[mt][nt], a0, a1, a2, a3, b0[nt], b1[nt]);
            }
        }
        __syncthreads();
    }

    #pragma unroll
    for (int mt = 0; mt < 2; mt++) {
        int r = row0 + wm + mt * 16 + gid;
        #pragma unroll
        for (int nt = 0; nt < 4; nt++) {
            int c = col0 + wn + nt * 8 + tig * 2;
            float2 v0 = {acc[mt][nt][0] + bias[c], acc[mt][nt][1] + bias[c + 1]};
            float2 v1 = {acc[mt][nt][2] + bias[c], acc[mt][nt][3] + bias[c + 1]};
            *(float2*)&out[(size_t)r * 768 + c]       = v0;
            *(float2*)&out[(size_t)(r + 8) * 768 + c] = v1;
        }
    }
}

// ---------------------------------------------------------------------------
// Fused score+exp tile (128x128, K=64, tf32, one-shot cp.async fill):
// E = exp(q.k/8 + maskterm) -> g_attn; partial row sums -> g_part.
// sQ @0 [m][d] str 68; sK @8704 [n][d] str 68; sPart @17408; sMask @17920.
// ---------------------------------------------------------------------------
__device__ void score_exp_tile(int tileIdx, const float* __restrict__ mask,
                               float* smem) {
    float* sQ = smem;
    float* sK = smem + 8704;
    float* sPart = smem + 17408;
    float* sMask = smem + 17920;

    const int bh = tileIdx >> 6;
    const int r  = tileIdx & 63;
    const int i0 = (r >> 3) * 128;
    const int j0 = (r & 7) * 128;
    const int b  = bh / 12, h = bh % 12;
    const float* qb = g_q + (size_t)b * S_ * 768 + h * 64;
    const float* kb = g_k + (size_t)b * S_ * 768 + h * 64;

    const int tid  = threadIdx.x;
    const int warp = tid >> 5, lane = tid & 31;
    const int gid  = lane >> 2, tig = lane & 3;
    const int wm   = (warp >> 2) * 32, wn = (warp & 3) * 32;

    const unsigned sQu = (unsigned)__cvta_generic_to_shared(sQ);
    const unsigned sKu = (unsigned)__cvta_generic_to_shared(sK);
    #pragma unroll
    for (int e = 0; e < 4; e++) {
        int idx = e * NTHR + tid;                 // 0..2047
        int m = idx >> 4, c = (idx & 15) * 4;     // 16 chunks/row (64 fl)
        cpa16(sQu + (unsigned)(m * 68 + c) * 4,
              &qb[(size_t)(i0 + m) * 768 + c]);
        cpa16(sKu + (unsigned)(m * 68 + c) * 4,
              &kb[(size_t)(j0 + m) * 768 + c]);
    }
    if (tid < 128) sMask[tid] = mask[(size_t)b * S_ + j0 + tid];
    cp_commit();
    cp_wait0();
    __syncthreads();

    float acc[2][4][4] = {};
    #pragma unroll
    for (int ks = 0; ks < 64; ks += 8) {
        unsigned b0[4], b1[4];
        #pragma unroll
        for (int nt = 0; nt < 4; nt++) {
            const float* bp = &sK[(wn + nt * 8 + gid) * 68 + ks + tig];
            b0[nt] = fu(bp[0]);
            b1[nt] = fu(bp[4]);
        }
        #pragma unroll
        for (int mt = 0; mt < 2; mt++) {
            const float* ap = &sQ[(wm + mt * 16 + gid) * 68 + ks + tig];
            unsigned a0 = fu(ap[0]);
            unsigned a1 = fu(ap[8 * 68]);
            unsigned a2 = fu(ap[4]);
            unsigned a3 = fu(ap[8 * 68 + 4]);
            #pragma unroll
            for (int nt = 0; nt < 4; nt++)
                mma_tf32(acc[mt][nt], a0, a1, a2, a3, b0[nt], b1[nt]);
        }
    }
    __syncthreads();

    const size_t base = (size_t)bh * S_ * S_;
    #pragma unroll
    for (int mt = 0; mt < 2; mt++) {
        int ri = i0 + wm + mt * 16 + gid;
        float rs0 = 0.0f, rs1 = 0.0f;
        #pragma unroll
        for (int nt = 0; nt < 4; nt++) {
            int lc = wn + nt * 8 + tig * 2;
            float mk0 = (1.0f - sMask[lc])     * -10000.0f;
            float mk1 = (1.0f - sMask[lc + 1]) * -10000.0f;
            float e0 = __expf(acc[mt][nt][0] * 0.125f + mk0);
            float e1 = __expf(acc[mt][nt][1] * 0.125f + mk1);
            float e2 = __expf(acc[mt][nt][2] * 0.125f + mk0);
            float e3 = __expf(acc[mt][nt][3] * 0.125f + mk1);
            rs0 += e0 + e1;
            rs1 += e2 + e3;
            float2 v0 = {e0, e1};
            float2 v1 = {e2, e3};
            *(float2*)&g_attn[base + (size_t)ri * S_ + j0 + lc]       = v0;
            *(float2*)&g_attn[base + (size_t)(ri + 8) * S_ + j0 + lc] = v1;
        }
        #pragma unroll
        for (int o = 1; o < 4; o <<= 1) {
            rs0 += __shfl_xor_sync(0xFFFFFFFFu, rs0, o);
            rs1 += __shfl_xor_sync(0xFFFFFFFFu, rs1, o);
        }
        if (tig == 0) {
            sPart[(warp & 3) * 128 + wm + mt * 16 + gid]     = rs0;
            sPart[(warp & 3) * 128 + wm + mt * 16 + gid + 8] = rs1;
        }
    }
    __syncthreads();

    if (tid < 128) {
        float p = sPart[tid] + sPart[128 + tid] + sPart[256 + tid] + sPart[384 + tid];
        g_part[((size_t)bh * S_ + i0 + tid) * 8 + (j0 >> 7)] = p;
    }
    __syncthreads();
}

// ---------------------------------------------------------------------------
// 128x64 ctx tile, BK=32, cp.async double-buffered, tf32:
//   O = inv * (E @ V); probs (E*inv, fp32) written to attn_out from smem.
// sP @0 [m][k] str 36, 2 bufs (4608 each); sV @9216 [k][n] str 68, 2 bufs
// (2176 each); sInv @13568 (128 floats).
// ---------------------------------------------------------------------------
__device__ __forceinline__ void ctx_fill(const float* __restrict__ ap,
                                         const float* __restrict__ vb,
                                         int i0, int jb,
                                         unsigned sPu, unsigned sVu, int tid) {
    #pragma unroll
    for (int e = 0; e < 2; e++) {
        int idx = e * NTHR + tid;                 // 0..1023
        int m = idx >> 3, c = (idx & 7) * 4;
        cpa16(sPu + (unsigned)(m * 36 + c) * 4,
              &ap[(size_t)(i0 + m) * S_ + jb + c]);
    }
    {
        int k = tid >> 4, c = (tid & 15) * 4;     // 512 chunks (32x64 fl)
        cpa16(sVu + (unsigned)(k * 68 + c) * 4,
              &vb[(size_t)(jb + k) * 768 + c]);
    }
    cp_commit();
}

__device__ void ctx_tile(int tileIdx, float* __restrict__ attn_out,
                         float* smem) {
    float* sP = smem;                 // 2 x 4608
    float* sV = smem + 9216;          // 2 x 2176
    float* sInv = smem + 13568;       // 128

    const int bh = tileIdx >> 3;
    const int i0 = (tileIdx & 7) * 128;
    const int b  = bh / 12, h = bh % 12;
    const float* ap = g_attn + (size_t)bh * S_ * S_;
    const float* vb = g_v + (size_t)b * S_ * 768 + h * 64;

    const int tid  = threadIdx.x;
    const int warp = tid >> 5, lane = tid & 31;
    const int gid  = lane >> 2, tig = lane & 3;
    const int wm   = (warp >> 2) * 32, wn = (warp & 3) * 16;

    const unsigned sPu = (unsigned)__cvta_generic_to_shared(sP);
    const unsigned sVu = (unsigned)__cvta_generic_to_shared(sV);

    if (tid < 128) sInv[tid] = g_inv[(size_t)bh * S_ + i0 + tid];

    float acc[2][2][4] = {};

    ctx_fill(ap, vb, i0, 0, sPu, sVu, tid);
    #pragma unroll 1
    for (int s = 0; s < 32; s++) {
        if (s + 1 < 32) {
            ctx_fill(ap, vb, i0, (s + 1) * 32,
                     sPu + ((s + 1) & 1) * 4608 * 4,
                     sVu + ((s + 1) & 1) * 2176 * 4, tid);
            cp_wait1();
        } else {
            cp_wait0();
        }
        __syncthreads();
        const float* cP = sP + (s & 1) * 4608;
        const float* cV = sV + (s & 1) * 2176;

        // normalized probs from the raw fp32 E in smem
        if (attn_out) {
            #pragma unroll
            for (int e = 0; e < 2; e++) {
                int idx = e * NTHR + tid;
                int m = idx >> 3, c = (idx & 7) * 4;
                float4 ev = *(const float4*)&cP[m * 36 + c];
                float iv = sInv[m];
                float4 pr = {ev.x * iv, ev.y * iv, ev.z * iv, ev.w * iv};
                *(float4*)&attn_out[(size_t)bh * S_ * S_ +
                                    (size_t)(i0 + m) * S_ + s * 32 + c] = pr;
            }
        }

        #pragma unroll
        for (int ks = 0; ks < 32; ks += 8) {
            unsigned b0[2], b1[2];
            #pragma unroll
            for (int nt = 0; nt < 2; nt++) {
                const float* bp = &cV[(ks + tig) * 68 + wn + nt * 8 + gid];
                b0[nt] = fu(bp[0]);
                b1[nt] = fu(bp[4 * 68]);
            }
            #pragma unroll
            for (int mt = 0; mt < 2; mt++) {
                const float* app = &cP[(wm + mt * 16 + gid) * 36 + ks + tig];
                unsigned a0 = fu(app[0]);
                unsigned a1 = fu(app[8 * 36]);
                unsigned a2 = fu(app[4]);
                unsigned a3 = fu(app[8 * 36 + 4]);
                #pragma unroll
                for (int nt = 0; nt < 2; nt++)
                    mma_tf32(acc[mt][nt], a0, a1, a2, a3, b0[nt], b1[nt]);
            }
        }
        __syncthreads();
    }

    #pragma unroll
    for (int mt = 0; mt < 2; mt++) {
        int sl = wm + mt * 16 + gid;
        int s = i0 + sl;
        float inv0 = sInv[sl];
        float inv1 = sInv[sl + 8];
        #pragma unroll
        for (int nt = 0; nt < 2; nt++) {
            int c = h * 64 + wn + nt * 8 + tig * 2;
            float2 v0 = {acc[mt][nt][0] * inv0, acc[mt][nt][1] * inv0};
            float2 v1 = {acc[mt][nt][2] * inv1, acc[mt][nt][3] * inv1};
            *(float2*)&g_ctx[(size_t)(b * S_ + s) * 768 + c]     = v0;
            *(float2*)&g_ctx[(size_t)(b * S_ + s + 8) * 768 + c] = v1;
        }
    }
    __syncthreads();
}

// ---------------------------------------------------------------------------
// The single fused kernel.
// ---------------------------------------------------------------------------
__global__ __launch_bounds__(NTHR, 2)
void fused_kernel(const float* __restrict__ query, const float* __restrict__ key,
                  const float* __restrict__ value, const float* __restrict__ mask,
                  const float* __restrict__ Wq, const float* __restrict__ bq,
                  const float* __restrict__ Wk, const float* __restrict__ bk,
                  const float* __restrict__ Wv, const float* __restrict__ bv,
                  const float* __restrict__ Wo, const float* __restrict__ bo,
                  const float* __restrict__ gamma, const float* __restrict__ beta,
                  float* __restrict__ out, float* __restrict__ attn_out) {
    extern __shared__ float smem[];
    const int tid  = threadIdx.x;
    const int warp = tid >> 5, lane = tid & 31;

    // ---- Phase 1: QKV projections (3 x 384 tile jobs, pipelined) ----
    for (int job = blockIdx.x; job < 3 * 384; job += NBLK) {
        int which = job / 384;
        int t = job % 384;
        const float* A  = (which == 0) ? query : (which == 1) ? key : value;
        const float* W  = (which == 0) ? Wq    : (which == 1) ? Wk  : Wv;
        const float* bb = (which == 0) ? bq    : (which == 1) ? bk  : bv;
        float* O        = (which == 0) ? g_q   : (which == 1) ? g_k : g_v;
        gemm_tile(A, W, bb, O, t, smem);
    }
    grid_barrier();

    // ---- Phase 2: fused score + exp + partial row sums (6144 jobs) ----
    for (int t = blockIdx.x; t < 6144; t += NBLK)
        score_exp_tile(t, mask, smem);
    grid_barrier();

    // ---- Phase 3: per-row inverse sums ----
    for (int row = blockIdx.x * NTHR + tid; row < 98304; row += NBLK * NTHR) {
        const float* pp = g_part + (size_t)row * 8;
        float4 a = *(const float4*)pp;
        float4 b4 = *(const float4*)(pp + 4);
        g_inv[row] = 1.0f / (a.x + a.y + a.z + a.w + b4.x + b4.y + b4.z + b4.w);
    }
    grid_barrier();

    // ---- Phase 4: context + normalized prob output (768 jobs, pipelined) ----
    for (int t = blockIdx.x; t < 768; t += NBLK)
        ctx_tile(t, attn_out, smem);
    grid_barrier();

    // ---- Phase 5: output projection (384 jobs, pipelined) ----
    for (int t = blockIdx.x; t < 384; t += NBLK)
        gemm_tile(g_ctx, Wo, bo, g_proj, t, smem);
    grid_barrier();

    // ---- Phase 6: residual + LayerNorm — warp per row ----
    for (int row = blockIdx.x * 16 + warp; row < MROWS; row += NBLK * 16) {
        const float* pp = g_proj + (size_t)row * 768;
        const float* op = query + (size_t)row * 768;

        float4 x[6];
        float sum = 0.0f;
        #pragma unroll
        for (int v = 0; v < 6; v++) {
            int off = v * 128 + lane * 4;
            float4 a = *(const float4*)&pp[off];
            float4 o = *(const float4*)&op[off];
            x[v].x = a.x + o.x; x[v].y = a.y + o.y;
            x[v].z = a.z + o.z; x[v].w = a.w + o.w;
            sum += x[v].x + x[v].y + x[v].z + x[v].w;
        }
        #pragma unroll
        for (int o = 16; o > 0; o >>= 1)
            sum += __shfl_xor_sync(0xFFFFFFFFu, sum, o);
        const float mu = sum * (1.0f / 768.0f);

        float var = 0.0f;
        #pragma unroll
        for (int v = 0; v < 6; v++) {
            float dx = x[v].x - mu, dy = x[v].y - mu;
            float dz = x[v].z - mu, dw = x[v].w - mu;
            var += dx * dx + dy * dy + dz * dz + dw * dw;
        }
        #pragma unroll
        for (int o = 16; o > 0; o >>= 1)
            var += __shfl_xor_sync(0xFFFFFFFFu, var, o);
        const float inv = rsqrtf(var * (1.0f / 768.0f) + 1e-8f);

        #pragma unroll
        for (int v = 0; v < 6; v++) {
            int off = v * 128 + lane * 4;
            float4 g = *(const float4*)&gamma[off];
            float4 bt = *(const float4*)&beta[off];
            float4 r;
            r.x = (x[v].x - mu) * inv * g.x + bt.x;
            r.y = (x[v].y - mu) * inv * g.y + bt.y;
            r.z = (x[v].z - mu) * inv * g.z + bt.z;
            r.w = (x[v].w - mu) * inv * g.w + bt.w;
            *(float4*)&out[(size_t)row * 768 + off] = r;
        }
    }
}

// ---------------------------------------------------------------------------
// Launch
// ---------------------------------------------------------------------------
extern "C" void kernel_launch(void* const* d_in, const int* in_sizes, int n_in,
                              void* d_out, int out_size) {
    const float* big[3]  = {0, 0, 0};
    const float* mats[4] = {0, 0, 0, 0};
    const float* vecs[6] = {0, 0, 0, 0, 0, 0};
    const float* mask = 0;
    int nb = 0, nm = 0, nv = 0;
    for (int i = 0; i < n_in; i++) {
        const float* p = (const float*)d_in[i];
        switch (in_sizes[i]) {
            case 6291456: if (nb < 3) big[nb++] = p;  break;
            case 589824:  if (nm < 4) mats[nm++] = p; break;
            case 768:     if (nv < 6) vecs[nv++] = p; break;
            case 8192:    mask = p;                   break;
            default: break;
        }
    }
    float* out = (float*)d_out;
    float* attn_out = ((long long)out_size >= (long long)BSD + BHSS)
                          ? (out + BSD) : 0;

    cudaFuncSetAttribute(fused_kernel,
                         cudaFuncAttributeMaxDynamicSharedMemorySize, DYN_SMEM);

    fused_kernel<<<NBLK, NTHR, DYN_SMEM>>>(big[0], big[1], big[2], mask,
                                           mats[0], vecs[0], mats[1], vecs[1],
                                           mats[2], vecs[2], mats[3], vecs[3],
                                           vecs[4], vecs[5], out, attn_out);
}

// round 11
// speedup vs baseline: 1.0606x; 1.0606x over previous
#include <cuda_runtime.h>
#include <cuda_bf16.h>

// Problem constants
#define B_    8
#define S_    1024
#define D_    768
#define H_    12
#define DK_   64
#define MROWS 8192                    // B*S
#define BSD   6291456                 // MROWS*D
#define BHSS  100663296LL             // B*H*S*S

#define NBLK  296                     // 2 per SM x 148 SMs, co-resident
#define NTHR  512
#define DYN_SMEM 72192                // score phase high-water: 18048 floats

// Device-global scratch — used ONLY within a single kernel launch.
__device__ float g_q[BSD];
__device__ float g_k[BSD];
__device__ float g_v[BSD];
__device__ float g_ctx[BSD];
__device__ float g_proj[BSD];
__device__ float g_attn[(size_t)BHSS];   // unnormalized exp(score)
__device__ float g_part[98304 * 8];      // per-row per-jtile partial sums
__device__ float g_inv[98304];           // per-row 1/sum

// Software grid barrier (generation counter; replay-safe).
__device__ unsigned g_bar_count;
__device__ unsigned g_bar_gen;

__device__ __forceinline__ void grid_barrier() {
    __syncthreads();
    if (threadIdx.x == 0) {
        __threadfence();
        unsigned gen = g_bar_gen;
        unsigned old = atomicAdd(&g_bar_count, 1u);
        if (old == (unsigned)(gridDim.x - 1)) {
            g_bar_count = 0;
            __threadfence();
            atomicAdd(&g_bar_gen, 1u);
        } else {
            while (atomicAdd(&g_bar_gen, 0u) == gen) { __nanosleep(64); }
        }
        __threadfence();
    }
    __syncthreads();
}

__device__ __forceinline__ float tf32r(float x) {
    unsigned u;
    asm("cvt.rna.tf32.f32 %0, %1;" : "=r"(u) : "f"(x));
    return __uint_as_float(u);
}
__device__ __forceinline__ float4 tf32r4(float4 v) {
    v.x = tf32r(v.x); v.y = tf32r(v.y); v.z = tf32r(v.z); v.w = tf32r(v.w);
    return v;
}
__device__ __forceinline__ unsigned bf2(float a, float b) {
    __nv_bfloat162 h = __floats2bfloat162_rn(a, b);
    return *(unsigned*)&h;
}

__device__ __forceinline__ void mma_tf32(float* acc, unsigned a0, unsigned a1,
                                         unsigned a2, unsigned a3,
                                         unsigned b0, unsigned b1) {
    asm volatile(
        "mma.sync.aligned.m16n8k8.row.col.f32.tf32.tf32.f32 "
        "{%0,%1,%2,%3}, {%4,%5,%6,%7}, {%8,%9}, {%0,%1,%2,%3};"
        : "+f"(acc[0]), "+f"(acc[1]), "+f"(acc[2]), "+f"(acc[3])
        : "r"(a0), "r"(a1), "r"(a2), "r"(a3), "r"(b0), "r"(b1));
}
__device__ __forceinline__ void mma_bf16(float* acc, unsigned a0, unsigned a1,
                                         unsigned a2, unsigned a3,
                                         unsigned b0, unsigned b1) {
    asm volatile(
        "mma.sync.aligned.m16n8k16.row.col.f32.bf16.bf16.f32 "
        "{%0,%1,%2,%3}, {%4,%5,%6,%7}, {%8,%9}, {%0,%1,%2,%3};"
        : "+f"(acc[0]), "+f"(acc[1]), "+f"(acc[2]), "+f"(acc[3])
        : "r"(a0), "r"(a1), "r"(a2), "r"(a3), "r"(b0), "r"(b1));
}

__device__ __forceinline__ void ldsm_x4(unsigned& r0, unsigned& r1,
                                        unsigned& r2, unsigned& r3,
                                        unsigned addr) {
    asm volatile("ldmatrix.sync.aligned.m8n8.x4.shared.b16 {%0,%1,%2,%3}, [%4];"
                 : "=r"(r0), "=r"(r1), "=r"(r2), "=r"(r3) : "r"(addr));
}
__device__ __forceinline__ void ldsm_x2(unsigned& r0, unsigned& r1,
                                        unsigned addr) {
    asm volatile("ldmatrix.sync.aligned.m8n8.x2.shared.b16 {%0,%1}, [%2];"
                 : "=r"(r0), "=r"(r1) : "r"(addr));
}
__device__ __forceinline__ unsigned smem_u32(const void* p) {
    return (unsigned)__cvta_generic_to_shared(p);
}

// ---------------------------------------------------------------------------
// 128x128 tf32 GEMM tile, BK=64, ldmatrix fragments.
// sA: [m][k] str 68 (tf32-RNA floats); sB: [n][k] str 68.
// 16 warps (4x4), 32x32 per warp. Used for QKV projections.
// ---------------------------------------------------------------------------
__device__ void gemm_tile_tf32(const float* __restrict__ A,
                               const float* __restrict__ W,
                               const float* __restrict__ bias,
                               float* __restrict__ out,
                               int tileIdx, float* sA, float* sB) {
    const int row0 = (tileIdx / 6) * 128;
    const int col0 = (tileIdx % 6) * 128;
    const int tid  = threadIdx.x;
    const int warp = tid >> 5, lane = tid & 31;
    const int gid  = lane >> 2, tig = lane & 3;
    const int wm   = (warp >> 2) * 32, wn = (warp & 3) * 32;

    // ldmatrix lane address bases
    const int mat = lane >> 3, r8 = lane & 7;
    const int lb  = lane & 15;
    const unsigned adrA0 = smem_u32(sA) +
        (((wm + (mat & 1) * 8 + r8) * 68 + (mat >> 1) * 4) << 2);
    const unsigned adrA1 = adrA0 + (16 * 68 << 2);
    const unsigned adrB0 = smem_u32(sB) +
        (((wn + (lb & 7)) * 68 + ((lb >> 3) & 1) * 4) << 2);

    float acc[2][4][4] = {};

    for (int k0 = 0; k0 < 768; k0 += 64) {
        #pragma unroll
        for (int e = 0; e < 4; e++) {
            int idx = (e * NTHR + tid) * 4;      // 0..8191
            int m = idx >> 6, k = idx & 63;
            float4 v = *(const float4*)&A[(size_t)(row0 + m) * 768 + k0 + k];
            *(float4*)&sA[m * 68 + k] = tf32r4(v);
        }
        {
            int n  = tid & 127;
            int kg = (tid >> 7) * 16;
            #pragma unroll
            for (int g = 0; g < 4; g++) {
                sB[n * 68 + kg + g * 4 + 0] = tf32r(W[(size_t)(k0 + kg + g * 4 + 0) * 768 + col0 + n]);
                sB[n * 68 + kg + g * 4 + 1] = tf32r(W[(size_t)(k0 + kg + g * 4 + 1) * 768 + col0 + n]);
                sB[n * 68 + kg + g * 4 + 2] = tf32r(W[(size_t)(k0 + kg + g * 4 + 2) * 768 + col0 + n]);
                sB[n * 68 + kg + g * 4 + 3] = tf32r(W[(size_t)(k0 + kg + g * 4 + 3) * 768 + col0 + n]);
            }
        }
        __syncthreads();

        #pragma unroll
        for (int ks = 0; ks < 64; ks += 8) {
            const unsigned boff = ks << 2;
            unsigned b0[4], b1[4];
            #pragma unroll
            for (int nt = 0; nt < 4; nt++)
                ldsm_x2(b0[nt], b1[nt], adrB0 + nt * (8 * 68 << 2) + boff);
            #pragma unroll
            for (int mt = 0; mt < 2; mt++) {
                unsigned a0, a1, a2, a3;
                ldsm_x4(a0, a1, a2, a3, (mt ? adrA1 : adrA0) + boff);
                #pragma unroll
                for (int nt = 0; nt < 4; nt++)
                    mma_tf32(acc[mt][nt], a0, a1, a2, a3, b0[nt], b1[nt]);
            }
        }
        __syncthreads();
    }

    #pragma unroll
    for (int mt = 0; mt < 2; mt++) {
        int r = row0 + wm + mt * 16 + gid;
        #pragma unroll
        for (int nt = 0; nt < 4; nt++) {
            int c = col0 + wn + nt * 8 + tig * 2;
            float2 v0 = {acc[mt][nt][0] + bias[c], acc[mt][nt][1] + bias[c + 1]};
            float2 v1 = {acc[mt][nt][2] + bias[c], acc[mt][nt][3] + bias[c + 1]};
            *(float2*)&out[(size_t)r * 768 + c]       = v0;
            *(float2*)&out[(size_t)(r + 8) * 768 + c] = v1;
        }
    }
}

// ---------------------------------------------------------------------------
// 64x128 bf16 GEMM tile (m16n8k16), BK=64, ldmatrix. O projection only.
// sA16: [m][72] b16 (64 rows); sB16: [n][72] b16 (128 rows).
// 16 warps (4x4), warp tile 16x32.
// ---------------------------------------------------------------------------
__device__ void gemm_tile_bf16(const float* __restrict__ A,
                               const float* __restrict__ W,
                               const float* __restrict__ bias,
                               float* __restrict__ out,
                               int tileIdx, float* smem) {
    __nv_bfloat16* sA16 = (__nv_bfloat16*)smem;            // 64*72
    __nv_bfloat16* sB16 = (__nv_bfloat16*)(smem + 2304);   // 128*72

    const int row0 = (tileIdx / 6) * 64;
    const int col0 = (tileIdx % 6) * 128;
    const int tid  = threadIdx.x;
    const int warp = tid >> 5, lane = tid & 31;
    const int gid  = lane >> 2, tig = lane & 3;
    const int wm   = (warp >> 2) * 16, wn = (warp & 3) * 32;

    const int mat = lane >> 3, r8 = lane & 7;
    const int lb  = lane & 15;
    const unsigned adrA0 = smem_u32(sA16) +
        (wm + (mat & 1) * 8 + r8) * 144 + (mat >> 1) * 16;
    const unsigned adrB0 = smem_u32(sB16) +
        (wn + (lb & 7)) * 144 + ((lb >> 3) & 1) * 16;

    float acc[4][4] = {};

    for (int k0 = 0; k0 < 768; k0 += 64) {
        #pragma unroll
        for (int e = 0; e < 2; e++) {
            int idx = (e * NTHR + tid) * 4;      // 0..4095
            int m = idx >> 6, k = idx & 63;
            float4 v = *(const float4*)&A[(size_t)(row0 + m) * 768 + k0 + k];
            uint2 u = {bf2(v.x, v.y), bf2(v.z, v.w)};
            *(uint2*)&sA16[m * 72 + k] = u;
        }
        {
            int n  = tid & 127;
            int kg = (tid >> 7) * 16;
            #pragma unroll
            for (int g = 0; g < 2; g++) {
                float w[8];
                #pragma unroll
                for (int i = 0; i < 8; i++)
                    w[i] = W[(size_t)(k0 + kg + g * 8 + i) * 768 + col0 + n];
                uint4 u = {bf2(w[0], w[1]), bf2(w[2], w[3]),
                           bf2(w[4], w[5]), bf2(w[6], w[7])};
                *(uint4*)&sB16[n * 72 + kg + g * 8] = u;
            }
        }
        __syncthreads();

        #pragma unroll
        for (int ks = 0; ks < 64; ks += 16) {
            const unsigned boff = ks << 1;
            unsigned b0[4], b1[4];
            #pragma unroll
            for (int nt = 0; nt < 4; nt++)
                ldsm_x2(b0[nt], b1[nt], adrB0 + nt * (8 * 144) + boff);
            unsigned a0, a1, a2, a3;
            ldsm_x4(a0, a1, a2, a3, adrA0 + boff);
            #pragma unroll
            for (int nt = 0; nt < 4; nt++)
                mma_bf16(acc[nt], a0, a1, a2, a3, b0[nt], b1[nt]);
        }
        __syncthreads();
    }

    {
        int r = row0 + wm + gid;
        #pragma unroll
        for (int nt = 0; nt < 4; nt++) {
            int c = col0 + wn + nt * 8 + tig * 2;
            float2 v0 = {acc[nt][0] + bias[c], acc[nt][1] + bias[c + 1]};
            float2 v1 = {acc[nt][2] + bias[c], acc[nt][3] + bias[c + 1]};
            *(float2*)&out[(size_t)r * 768 + c]       = v0;
            *(float2*)&out[(size_t)(r + 8) * 768 + c] = v1;
        }
    }
}

// ---------------------------------------------------------------------------
// Fused score+exp tile (128x128, K=64, tf32, ldmatrix).
// sQ: [m][68]; sK: [n][68]; sPart: [4][128]; sMask: [128].
// ---------------------------------------------------------------------------
__device__ void score_exp_tile(int tileIdx, const float* __restrict__ mask,
                               float* sQ, float* sK, float* sPart, float* sMask) {
    const int bh = tileIdx >> 6;
    const int r  = tileIdx & 63;
    const int i0 = (r >> 3) * 128;
    const int j0 = (r & 7) * 128;
    const int b  = bh / 12, h = bh % 12;
    const float* qb = g_q + (size_t)b * S_ * 768 + h * 64;
    const float* kb = g_k + (size_t)b * S_ * 768 + h * 64;

    const int tid  = threadIdx.x;
    const int warp = tid >> 5, lane = tid & 31;
    const int gid  = lane >> 2, tig = lane & 3;
    const int wm   = (warp >> 2) * 32, wn = (warp & 3) * 32;

    const int mat = lane >> 3, r8 = lane & 7;
    const int lb  = lane & 15;
    const unsigned adrA0 = smem_u32(sQ) +
        (((wm + (mat & 1) * 8 + r8) * 68 + (mat >> 1) * 4) << 2);
    const unsigned adrA1 = adrA0 + (16 * 68 << 2);
    const unsigned adrB0 = smem_u32(sK) +
        (((wn + (lb & 7)) * 68 + ((lb >> 3) & 1) * 4) << 2);

    #pragma unroll
    for (int e = 0; e < 4; e++) {
        int idx = (e * NTHR + tid) * 4;
        int m = idx >> 6, d = idx & 63;
        *(float4*)&sQ[m * 68 + d] =
            tf32r4(*(const float4*)&qb[(size_t)(i0 + m) * 768 + d]);
        *(float4*)&sK[m * 68 + d] =
            tf32r4(*(const float4*)&kb[(size_t)(j0 + m) * 768 + d]);
    }
    if (tid < 128) sMask[tid] = mask[(size_t)b * S_ + j0 + tid];
    __syncthreads();

    float acc[2][4][4] = {};
    #pragma unroll
    for (int ks = 0; ks < 64; ks += 8) {
        const unsigned boff = ks << 2;
        unsigned b0[4], b1[4];
        #pragma unroll
        for (int nt = 0; nt < 4; nt++)
            ldsm_x2(b0[nt], b1[nt], adrB0 + nt * (8 * 68 << 2) + boff);
        #pragma unroll
        for (int mt = 0; mt < 2; mt++) {
            unsigned a0, a1, a2, a3;
            ldsm_x4(a0, a1, a2, a3, (mt ? adrA1 : adrA0) + boff);
            #pragma unroll
            for (int nt = 0; nt < 4; nt++)
                mma_tf32(acc[mt][nt], a0, a1, a2, a3, b0[nt], b1[nt]);
        }
    }
    __syncthreads();

    const size_t base = (size_t)bh * S_ * S_;
    #pragma unroll
    for (int mt = 0; mt < 2; mt++) {
        int ri = i0 + wm + mt * 16 + gid;
        float rs0 = 0.0f, rs1 = 0.0f;
        #pragma unroll
        for (int nt = 0; nt < 4; nt++) {
            int lc = wn + nt * 8 + tig * 2;
            float mk0 = (1.0f - sMask[lc])     * -10000.0f;
            float mk1 = (1.0f - sMask[lc + 1]) * -10000.0f;
            float e0 = __expf(acc[mt][nt][0] * 0.125f + mk0);
            float e1 = __expf(acc[mt][nt][1] * 0.125f + mk1);
            float e2 = __expf(acc[mt][nt][2] * 0.125f + mk0);
            float e3 = __expf(acc[mt][nt][3] * 0.125f + mk1);
            rs0 += e0 + e1;
            rs1 += e2 + e3;
            float2 v0 = {e0, e1};
            float2 v1 = {e2, e3};
            *(float2*)&g_attn[base + (size_t)ri * S_ + j0 + lc]       = v0;
            *(float2*)&g_attn[base + (size_t)(ri + 8) * S_ + j0 + lc] = v1;
        }
        #pragma unroll
        for (int o = 1; o < 4; o <<= 1) {
            rs0 += __shfl_xor_sync(0xFFFFFFFFu, rs0, o);
            rs1 += __shfl_xor_sync(0xFFFFFFFFu, rs1, o);
        }
        if (tig == 0) {
            sPart[(warp & 3) * 128 + wm + mt * 16 + gid]     = rs0;
            sPart[(warp & 3) * 128 + wm + mt * 16 + gid + 8] = rs1;
        }
    }
    __syncthreads();

    if (tid < 128) {
        float p = sPart[tid] + sPart[128 + tid] + sPart[256 + tid] + sPart[384 + tid];
        g_part[((size_t)bh * S_ + i0 + tid) * 8 + (j0 >> 7)] = p;
    }
    __syncthreads();
}

// ---------------------------------------------------------------------------
// 128x64 ctx tile, BK=64, bf16 mma + ldmatrix: O = inv * (E @ V).
// Probs (E*inv, fp32) written during the fp32 E read (accuracy unchanged).
// sP: bf16 [128][72]; sV: bf16 [64][72]; sInv: float[128].
// ---------------------------------------------------------------------------
__device__ void ctx_tile(int tileIdx, float* __restrict__ attn_out,
                         float* smem) {
    __nv_bfloat16* sP = (__nv_bfloat16*)smem;              // 128*72 bf16
    __nv_bfloat16* sV = (__nv_bfloat16*)(smem + 4608);     // 64*72 bf16
    float* sInv = smem + 6912;                             // 128 floats

    const int bh = tileIdx >> 3;
    const int i0 = (tileIdx & 7) * 128;
    const int b  = bh / 12, h = bh % 12;
    const float* ap = g_attn + (size_t)bh * S_ * S_;
    const float* vb = g_v + (size_t)b * S_ * 768 + h * 64;

    const int tid  = threadIdx.x;
    const int warp = tid >> 5, lane = tid & 31;
    const int gid  = lane >> 2, tig = lane & 3;
    const int wm   = (warp >> 2) * 32, wn = (warp & 3) * 16;

    const int mat = lane >> 3, r8 = lane & 7;
    const int lb  = lane & 15;
    const unsigned adrA0 = smem_u32(sP) +
        (wm + (mat & 1) * 8 + r8) * 144 + (mat >> 1) * 16;
    const unsigned adrA1 = adrA0 + 16 * 144;
    const unsigned adrB0 = smem_u32(sV) +
        (wn + (lb & 7)) * 144 + ((lb >> 3) & 1) * 16;

    if (tid < 128) sInv[tid] = g_inv[(size_t)bh * S_ + i0 + tid];
    __syncthreads();

    float acc[2][2][4] = {};

    for (int jb = 0; jb < S_; jb += 64) {
        #pragma unroll
        for (int e = 0; e < 4; e++) {
            int idx = (e * NTHR + tid) * 4;
            int m = idx >> 6, k = idx & 63;
            size_t off = (size_t)(i0 + m) * S_ + jb + k;
            float4 ev = *(const float4*)&ap[off];
            if (attn_out) {
                float iv = sInv[m];
                float4 pr = {ev.x * iv, ev.y * iv, ev.z * iv, ev.w * iv};
                *(float4*)&attn_out[(size_t)bh * S_ * S_ + off] = pr;
            }
            uint2 u = {bf2(ev.x, ev.y), bf2(ev.z, ev.w)};
            *(uint2*)&sP[m * 72 + k] = u;
        }
        {
            int n  = tid & 63;
            int kg = (tid >> 6) * 8;
            float w[8];
            #pragma unroll
            for (int i = 0; i < 8; i++)
                w[i] = vb[(size_t)(jb + kg + i) * 768 + n];
            uint4 u = {bf2(w[0], w[1]), bf2(w[2], w[3]),
                       bf2(w[4], w[5]), bf2(w[6], w[7])};
            *(uint4*)&sV[n * 72 + kg] = u;
        }
        __syncthreads();

        #pragma unroll
        for (int ks = 0; ks < 64; ks += 16) {
            const unsigned boff = ks << 1;
            unsigned b0[2], b1[2];
            #pragma unroll
            for (int nt = 0; nt < 2; nt++)
                ldsm_x2(b0[nt], b1[nt], adrB0 + nt * (8 * 144) + boff);
            #pragma unroll
            for (int mt = 0; mt < 2; mt++) {
                unsigned a0, a1, a2, a3;
                ldsm_x4(a0, a1, a2, a3, (mt ? adrA1 : adrA0) + boff);
                #pragma unroll
                for (int nt = 0; nt < 2; nt++)
                    mma_bf16(acc[mt][nt], a0, a1, a2, a3, b0[nt], b1[nt]);
            }
        }
        __syncthreads();
    }

    #pragma unroll
    for (int mt = 0; mt < 2; mt++) {
        int sl = wm + mt * 16 + gid;
        int s = i0 + sl;
        float inv0 = sInv[sl];
        float inv1 = sInv[sl + 8];
        #pragma unroll
        for (int nt = 0; nt < 2; nt++) {
            int c = h * 64 + wn + nt * 8 + tig * 2;
            float2 v0 = {acc[mt][nt][0] * inv0, acc[mt][nt][1] * inv0};
            float2 v1 = {acc[mt][nt][2] * inv1, acc[mt][nt][3] * inv1};
            *(float2*)&g_ctx[(size_t)(b * S_ + s) * 768 + c]     = v0;
            *(float2*)&g_ctx[(size_t)(b * S_ + s + 8) * 768 + c] = v1;
        }
    }
    __syncthreads();
}

// ---------------------------------------------------------------------------
// The single fused kernel.
// ---------------------------------------------------------------------------
__global__ __launch_bounds__(NTHR, 2)
void fused_kernel(const float* __restrict__ query, const float* __restrict__ key,
                  const float* __restrict__ value, const float* __restrict__ mask,
                  const float* __restrict__ Wq, const float* __restrict__ bq,
                  const float* __restrict__ Wk, const float* __restrict__ bk,
                  const float* __restrict__ Wv, const float* __restrict__ bv,
                  const float* __restrict__ Wo, const float* __restrict__ bo,
                  const float* __restrict__ gamma, const float* __restrict__ beta,
                  float* __restrict__ out, float* __restrict__ attn_out) {
    extern __shared__ float smem[];
    const int tid  = threadIdx.x;
    const int warp = tid >> 5, lane = tid & 31;

    // ---- Phase 1: QKV projections (3 x 384 tile jobs, tf32) ----
    for (int job = blockIdx.x; job < 3 * 384; job += NBLK) {
        int which = job / 384;
        int t = job % 384;
        const float* A  = (which == 0) ? query : (which == 1) ? key : value;
        const float* W  = (which == 0) ? Wq    : (which == 1) ? Wk  : Wv;
        const float* bb = (which == 0) ? bq    : (which == 1) ? bk  : bv;
        float* O        = (which == 0) ? g_q   : (which == 1) ? g_k : g_v;
        gemm_tile_tf32(A, W, bb, O, t, smem, smem + 8704);
    }
    grid_barrier();

    // ---- Phase 2: fused score + exp + partial row sums (6144 jobs) ----
    for (int t = blockIdx.x; t < 6144; t += NBLK)
        score_exp_tile(t, mask, smem, smem + 8704, smem + 17408, smem + 17920);
    grid_barrier();

    // ---- Phase 3: per-row inverse sums ----
    for (int row = blockIdx.x * NTHR + tid; row < 98304; row += NBLK * NTHR) {
        const float* pp = g_part + (size_t)row * 8;
        float4 a = *(const float4*)pp;
        float4 b4 = *(const float4*)(pp + 4);
        g_inv[row] = 1.0f / (a.x + a.y + a.z + a.w + b4.x + b4.y + b4.z + b4.w);
    }
    grid_barrier();

    // ---- Phase 4: context + normalized prob output (768 jobs, bf16) ----
    for (int t = blockIdx.x; t < 768; t += NBLK)
        ctx_tile(t, attn_out, smem);
    grid_barrier();

    // ---- Phase 5: output projection (768 jobs, bf16, 64x128 tiles) ----
    for (int t = blockIdx.x; t < 768; t += NBLK)
        gemm_tile_bf16(g_ctx, Wo, bo, g_proj, t, smem);
    grid_barrier();

    // ---- Phase 6: residual + LayerNorm — warp per row ----
    for (int row = blockIdx.x * 16 + warp; row < MROWS; row += NBLK * 16) {
        const float* pp = g_proj + (size_t)row * 768;
        const float* op = query + (size_t)row * 768;

        float4 x[6];
        float sum = 0.0f;
        #pragma unroll
        for (int v = 0; v < 6; v++) {
            int off = v * 128 + lane * 4;
            float4 a = *(const float4*)&pp[off];
            float4 o = *(const float4*)&op[off];
            x[v].x = a.x + o.x; x[v].y = a.y + o.y;
            x[v].z = a.z + o.z; x[v].w = a.w + o.w;
            sum += x[v].x + x[v].y + x[v].z + x[v].w;
        }
        #pragma unroll
        for (int o = 16; o > 0; o >>= 1)
            sum += __shfl_xor_sync(0xFFFFFFFFu, sum, o);
        const float mu = sum * (1.0f / 768.0f);

        float var = 0.0f;
        #pragma unroll
        for (int v = 0; v < 6; v++) {
            float dx = x[v].x - mu, dy = x[v].y - mu;
            float dz = x[v].z - mu, dw = x[v].w - mu;
            var += dx * dx + dy * dy + dz * dz + dw * dw;
        }
        #pragma unroll
        for (int o = 16; o > 0; o >>= 1)
            var += __shfl_xor_sync(0xFFFFFFFFu, var, o);
        const float inv = rsqrtf(var * (1.0f / 768.0f) + 1e-8f);

        #pragma unroll
        for (int v = 0; v < 6; v++) {
            int off = v * 128 + lane * 4;
            float4 g = *(const float4*)&gamma[off];
            float4 bt = *(const float4*)&beta[off];
            float4 r;
            r.x = (x[v].x - mu) * inv * g.x + bt.x;
            r.y = (x[v].y - mu) * inv * g.y + bt.y;
            r.z = (x[v].z - mu) * inv * g.z + bt.z;
            r.w = (x[v].w - mu) * inv * g.w + bt.w;
            *(float4*)&out[(size_t)row * 768 + off] = r;
        }
    }
}

// ---------------------------------------------------------------------------
// Launch
// ---------------------------------------------------------------------------
extern "C" void kernel_launch(void* const* d_in, const int* in_sizes, int n_in,
                              void* d_out, int out_size) {
    const float* big[3]  = {0, 0, 0};
    const float* mats[4] = {0, 0, 0, 0};
    const float* vecs[6] = {0, 0, 0, 0, 0, 0};
    const float* mask = 0;
    int nb = 0, nm = 0, nv = 0;
    for (int i = 0; i < n_in; i++) {
        const float* p = (const float*)d_in[i];
        switch (in_sizes[i]) {
            case 6291456: if (nb < 3) big[nb++] = p;  break;
            case 589824:  if (nm < 4) mats[nm++] = p; break;
            case 768:     if (nv < 6) vecs[nv++] = p; break;
            case 8192:    mask = p;                   break;
            default: break;
        }
    }
    float* out = (float*)d_out;
    float* attn_out = ((long long)out_size >= (long long)BSD + BHSS)
                          ? (out + BSD) : 0;

    cudaFuncSetAttribute(fused_kernel,
                         cudaFuncAttributeMaxDynamicSharedMemorySize, DYN_SMEM);

    fused_kernel<<<NBLK, NTHR, DYN_SMEM>>>(big[0], big[1], big[2], mask,
                                           mats[0], vecs[0], mats[1], vecs[1],
                                           mats[2], vecs[2], mats[3], vecs[3],
                                           vecs[4], vecs[5], out, attn_out);
}

// round 12
// speedup vs baseline: 1.0857x; 1.0237x over previous
#include <cuda_runtime.h>
#include <cuda_bf16.h>

// Problem constants
#define B_    8
#define S_    1024
#define D_    768
#define H_    12
#define MROWS 8192                    // B*S
#define BSD   6291456                 // MROWS*D
#define BHSS  100663296LL             // B*H*S*S

#define NBLK  296                     // 2 per SM x 148 SMs, co-resident
#define NTHR  512
#define DYN_SMEM 80640                // ctx+probs pass high-water: 20160 floats

// Device-global scratch — used ONLY within a single kernel launch.
__device__ float g_q[BSD];
__device__ float g_k[BSD];
__device__ float g_v[BSD];
__device__ float g_ctx[BSD];
__device__ float g_proj[BSD];
__device__ float g_inv[98304];           // per-row 1/sum

// Software grid barrier (generation counter; replay-safe).
__device__ unsigned g_bar_count;
__device__ unsigned g_bar_gen;

__device__ __forceinline__ void grid_barrier() {
    __syncthreads();
    if (threadIdx.x == 0) {
        __threadfence();
        unsigned gen = g_bar_gen;
        unsigned old = atomicAdd(&g_bar_count, 1u);
        if (old == (unsigned)(gridDim.x - 1)) {
            g_bar_count = 0;
            __threadfence();
            atomicAdd(&g_bar_gen, 1u);
        } else {
            while (atomicAdd(&g_bar_gen, 0u) == gen) { __nanosleep(64); }
        }
        __threadfence();
    }
    __syncthreads();
}

__device__ __forceinline__ float tf32r(float x) {
    unsigned u;
    asm("cvt.rna.tf32.f32 %0, %1;" : "=r"(u) : "f"(x));
    return __uint_as_float(u);
}
__device__ __forceinline__ float4 tf32r4(float4 v) {
    v.x = tf32r(v.x); v.y = tf32r(v.y); v.z = tf32r(v.z); v.w = tf32r(v.w);
    return v;
}
__device__ __forceinline__ unsigned bf2(float a, float b) {
    __nv_bfloat162 h = __floats2bfloat162_rn(a, b);
    return *(unsigned*)&h;
}

__device__ __forceinline__ void mma_tf32(float* acc, unsigned a0, unsigned a1,
                                         unsigned a2, unsigned a3,
                                         unsigned b0, unsigned b1) {
    asm volatile(
        "mma.sync.aligned.m16n8k8.row.col.f32.tf32.tf32.f32 "
        "{%0,%1,%2,%3}, {%4,%5,%6,%7}, {%8,%9}, {%0,%1,%2,%3};"
        : "+f"(acc[0]), "+f"(acc[1]), "+f"(acc[2]), "+f"(acc[3])
        : "r"(a0), "r"(a1), "r"(a2), "r"(a3), "r"(b0), "r"(b1));
}
__device__ __forceinline__ void mma_bf16(float* acc, unsigned a0, unsigned a1,
                                         unsigned a2, unsigned a3,
                                         unsigned b0, unsigned b1) {
    asm volatile(
        "mma.sync.aligned.m16n8k16.row.col.f32.bf16.bf16.f32 "
        "{%0,%1,%2,%3}, {%4,%5,%6,%7}, {%8,%9}, {%0,%1,%2,%3};"
        : "+f"(acc[0]), "+f"(acc[1]), "+f"(acc[2]), "+f"(acc[3])
        : "r"(a0), "r"(a1), "r"(a2), "r"(a3), "r"(b0), "r"(b1));
}

__device__ __forceinline__ void ldsm_x4(unsigned& r0, unsigned& r1,
                                        unsigned& r2, unsigned& r3,
                                        unsigned addr) {
    asm volatile("ldmatrix.sync.aligned.m8n8.x4.shared.b16 {%0,%1,%2,%3}, [%4];"
                 : "=r"(r0), "=r"(r1), "=r"(r2), "=r"(r3) : "r"(addr));
}
__device__ __forceinline__ void ldsm_x2(unsigned& r0, unsigned& r1,
                                        unsigned addr) {
    asm volatile("ldmatrix.sync.aligned.m8n8.x2.shared.b16 {%0,%1}, [%2];"
                 : "=r"(r0), "=r"(r1) : "r"(addr));
}
__device__ __forceinline__ unsigned smem_u32(const void* p) {
    return (unsigned)__cvta_generic_to_shared(p);
}

// ---------------------------------------------------------------------------
// 128x128 tf32 GEMM tile, BK=64, ldmatrix fragments (QKV projections).
// ---------------------------------------------------------------------------
__device__ void gemm_tile_tf32(const float* __restrict__ A,
                               const float* __restrict__ W,
                               const float* __restrict__ bias,
                               float* __restrict__ out,
                               int tileIdx, float* sA, float* sB) {
    const int row0 = (tileIdx / 6) * 128;
    const int col0 = (tileIdx % 6) * 128;
    const int tid  = threadIdx.x;
    const int warp = tid >> 5, lane = tid & 31;
    const int gid  = lane >> 2, tig = lane & 3;
    const int wm   = (warp >> 2) * 32, wn = (warp & 3) * 32;

    const int mat = lane >> 3, r8 = lane & 7;
    const int lb  = lane & 15;
    const unsigned adrA0 = smem_u32(sA) +
        (((wm + (mat & 1) * 8 + r8) * 68 + (mat >> 1) * 4) << 2);
    const unsigned adrA1 = adrA0 + (16 * 68 << 2);
    const unsigned adrB0 = smem_u32(sB) +
        (((wn + (lb & 7)) * 68 + ((lb >> 3) & 1) * 4) << 2);

    float acc[2][4][4] = {};

    for (int k0 = 0; k0 < 768; k0 += 64) {
        #pragma unroll
        for (int e = 0; e < 4; e++) {
            int idx = (e * NTHR + tid) * 4;
            int m = idx >> 6, k = idx & 63;
            float4 v = *(const float4*)&A[(size_t)(row0 + m) * 768 + k0 + k];
            *(float4*)&sA[m * 68 + k] = tf32r4(v);
        }
        {
            int n  = tid & 127;
            int kg = (tid >> 7) * 16;
            #pragma unroll
            for (int g = 0; g < 4; g++) {
                sB[n * 68 + kg + g * 4 + 0] = tf32r(W[(size_t)(k0 + kg + g * 4 + 0) * 768 + col0 + n]);
                sB[n * 68 + kg + g * 4 + 1] = tf32r(W[(size_t)(k0 + kg + g * 4 + 1) * 768 + col0 + n]);
                sB[n * 68 + kg + g * 4 + 2] = tf32r(W[(size_t)(k0 + kg + g * 4 + 2) * 768 + col0 + n]);
                sB[n * 68 + kg + g * 4 + 3] = tf32r(W[(size_t)(k0 + kg + g * 4 + 3) * 768 + col0 + n]);
            }
        }
        __syncthreads();

        #pragma unroll
        for (int ks = 0; ks < 64; ks += 8) {
            const unsigned boff = ks << 2;
            unsigned b0[4], b1[4];
            #pragma unroll
            for (int nt = 0; nt < 4; nt++)
                ldsm_x2(b0[nt], b1[nt], adrB0 + nt * (8 * 68 << 2) + boff);
            #pragma unroll
            for (int mt = 0; mt < 2; mt++) {
                unsigned a0, a1, a2, a3;
                ldsm_x4(a0, a1, a2, a3, (mt ? adrA1 : adrA0) + boff);
                #pragma unroll
                for (int nt = 0; nt < 4; nt++)
                    mma_tf32(acc[mt][nt], a0, a1, a2, a3, b0[nt], b1[nt]);
            }
        }
        __syncthreads();
    }

    #pragma unroll
    for (int mt = 0; mt < 2; mt++) {
        int r = row0 + wm + mt * 16 + gid;
        #pragma unroll
        for (int nt = 0; nt < 4; nt++) {
            int c = col0 + wn + nt * 8 + tig * 2;
            float2 v0 = {acc[mt][nt][0] + bias[c], acc[mt][nt][1] + bias[c + 1]};
            float2 v1 = {acc[mt][nt][2] + bias[c], acc[mt][nt][3] + bias[c + 1]};
            *(float2*)&out[(size_t)r * 768 + c]       = v0;
            *(float2*)&out[(size_t)(r + 8) * 768 + c] = v1;
        }
    }
}

// ---------------------------------------------------------------------------
// 64x128 bf16 GEMM tile (m16n8k16), BK=64, ldmatrix. O projection only.
// ---------------------------------------------------------------------------
__device__ void gemm_tile_bf16(const float* __restrict__ A,
                               const float* __restrict__ W,
                               const float* __restrict__ bias,
                               float* __restrict__ out,
                               int tileIdx, float* smem) {
    __nv_bfloat16* sA16 = (__nv_bfloat16*)smem;            // 64*72
    __nv_bfloat16* sB16 = (__nv_bfloat16*)(smem + 2304);   // 128*72

    const int row0 = (tileIdx / 6) * 64;
    const int col0 = (tileIdx % 6) * 128;
    const int tid  = threadIdx.x;
    const int warp = tid >> 5, lane = tid & 31;
    const int gid  = lane >> 2, tig = lane & 3;
    const int wm   = (warp >> 2) * 16, wn = (warp & 3) * 32;

    const int mat = lane >> 3, r8 = lane & 7;
    const int lb  = lane & 15;
    const unsigned adrA0 = smem_u32(sA16) +
        (wm + (mat & 1) * 8 + r8) * 144 + (mat >> 1) * 16;
    const unsigned adrB0 = smem_u32(sB16) +
        (wn + (lb & 7)) * 144 + ((lb >> 3) & 1) * 16;

    float acc[4][4] = {};

    for (int k0 = 0; k0 < 768; k0 += 64) {
        #pragma unroll
        for (int e = 0; e < 2; e++) {
            int idx = (e * NTHR + tid) * 4;
            int m = idx >> 6, k = idx & 63;
            float4 v = *(const float4*)&A[(size_t)(row0 + m) * 768 + k0 + k];
            uint2 u = {bf2(v.x, v.y), bf2(v.z, v.w)};
            *(uint2*)&sA16[m * 72 + k] = u;
        }
        {
            int n  = tid & 127;
            int kg = (tid >> 7) * 16;
            #pragma unroll
            for (int g = 0; g < 2; g++) {
                float w[8];
                #pragma unroll
                for (int i = 0; i < 8; i++)
                    w[i] = W[(size_t)(k0 + kg + g * 8 + i) * 768 + col0 + n];
                uint4 u = {bf2(w[0], w[1]), bf2(w[2], w[3]),
                           bf2(w[4], w[5]), bf2(w[6], w[7])};
                *(uint4*)&sB16[n * 72 + kg + g * 8] = u;
            }
        }
        __syncthreads();

        #pragma unroll
        for (int ks = 0; ks < 64; ks += 16) {
            const unsigned boff = ks << 1;
            unsigned b0[4], b1[4];
            #pragma unroll
            for (int nt = 0; nt < 4; nt++)
                ldsm_x2(b0[nt], b1[nt], adrB0 + nt * (8 * 144) + boff);
            unsigned a0, a1, a2, a3;
            ldsm_x4(a0, a1, a2, a3, adrA0 + boff);
            #pragma unroll
            for (int nt = 0; nt < 4; nt++)
                mma_bf16(acc[nt], a0, a1, a2, a3, b0[nt], b1[nt]);
        }
        __syncthreads();
    }

    {
        int r = row0 + wm + gid;
        #pragma unroll
        for (int nt = 0; nt < 4; nt++) {
            int c = col0 + wn + nt * 8 + tig * 2;
            float2 v0 = {acc[nt][0] + bias[c], acc[nt][1] + bias[c + 1]};
            float2 v1 = {acc[nt][2] + bias[c], acc[nt][3] + bias[c + 1]};
            *(float2*)&out[(size_t)r * 768 + c]       = v0;
            *(float2*)&out[(size_t)(r + 8) * 768 + c] = v1;
        }
    }
}

// ---------------------------------------------------------------------------
// SUM PASS: job = (bh, i0). Q tile resident; loop 8 K-tiles (128 wide);
// scores -> exp -> row sums (registers) -> g_inv. No E stored.
// smem: sQ @0 (8704), sK @8704 (8704), sMask @17408 (128), sRed @17536 (512)
// ---------------------------------------------------------------------------
__device__ void sum_pass(int job, const float* __restrict__ mask, float* smem) {
    float* sQ = smem;
    float* sK = smem + 8704;
    float* sMask = smem + 17408;
    float* sRed = smem + 17536;

    const int bh = job >> 3;
    const int i0 = (job & 7) * 128;
    const int b  = bh / 12, h = bh % 12;
    const float* qb = g_q + (size_t)b * S_ * 768 + h * 64;
    const float* kb = g_k + (size_t)b * S_ * 768 + h * 64;

    const int tid  = threadIdx.x;
    const int warp = tid >> 5, lane = tid & 31;
    const int gid  = lane >> 2, tig = lane & 3;
    const int wm   = (warp >> 2) * 32, wn = (warp & 3) * 32;

    const int mat = lane >> 3, r8 = lane & 7;
    const int lb  = lane & 15;
    const unsigned adrA0 = smem_u32(sQ) +
        (((wm + (mat & 1) * 8 + r8) * 68 + (mat >> 1) * 4) << 2);
    const unsigned adrA1 = adrA0 + (16 * 68 << 2);
    const unsigned adrB0 = smem_u32(sK) +
        (((wn + (lb & 7)) * 68 + ((lb >> 3) & 1) * 4) << 2);

    // Fill Q tile once
    #pragma unroll
    for (int e = 0; e < 4; e++) {
        int idx = e * NTHR + tid;                  // 0..2047
        int m = idx >> 4, d = (idx & 15) * 4;
        *(float4*)&sQ[m * 68 + d] =
            tf32r4(*(const float4*)&qb[(size_t)(i0 + m) * 768 + d]);
    }

    float rs[2][2] = {};

    for (int jt = 0; jt < 8; jt++) {
        int j0 = jt * 128;
        __syncthreads();                           // guard sK/sMask overwrite
        #pragma unroll
        for (int e = 0; e < 4; e++) {
            int idx = e * NTHR + tid;
            int m = idx >> 4, d = (idx & 15) * 4;
            *(float4*)&sK[m * 68 + d] =
                tf32r4(*(const float4*)&kb[(size_t)(j0 + m) * 768 + d]);
        }
        if (tid < 128) sMask[tid] = mask[(size_t)b * S_ + j0 + tid];
        __syncthreads();

        float acc[2][4][4] = {};
        #pragma unroll
        for (int ks = 0; ks < 64; ks += 8) {
            const unsigned boff = ks << 2;
            unsigned b0[4], b1[4];
            #pragma unroll
            for (int nt = 0; nt < 4; nt++)
                ldsm_x2(b0[nt], b1[nt], adrB0 + nt * (8 * 68 << 2) + boff);
            #pragma unroll
            for (int mt = 0; mt < 2; mt++) {
                unsigned a0, a1, a2, a3;
                ldsm_x4(a0, a1, a2, a3, (mt ? adrA1 : adrA0) + boff);
                #pragma unroll
                for (int nt = 0; nt < 4; nt++)
                    mma_tf32(acc[mt][nt], a0, a1, a2, a3, b0[nt], b1[nt]);
            }
        }

        #pragma unroll
        for (int mt = 0; mt < 2; mt++) {
            #pragma unroll
            for (int nt = 0; nt < 4; nt++) {
                int lc = wn + nt * 8 + tig * 2;
                float mk0 = (1.0f - sMask[lc])     * -10000.0f;
                float mk1 = (1.0f - sMask[lc + 1]) * -10000.0f;
                rs[mt][0] += __expf(acc[mt][nt][0] * 0.125f + mk0)
                           + __expf(acc[mt][nt][1] * 0.125f + mk1);
                rs[mt][1] += __expf(acc[mt][nt][2] * 0.125f + mk0)
                           + __expf(acc[mt][nt][3] * 0.125f + mk1);
            }
        }
    }

    // reduce over tig lanes
    #pragma unroll
    for (int o = 1; o < 4; o <<= 1) {
        rs[0][0] += __shfl_xor_sync(0xFFFFFFFFu, rs[0][0], o);
        rs[0][1] += __shfl_xor_sync(0xFFFFFFFFu, rs[0][1], o);
        rs[1][0] += __shfl_xor_sync(0xFFFFFFFFu, rs[1][0], o);
        rs[1][1] += __shfl_xor_sync(0xFFFFFFFFu, rs[1][1], o);
    }
    __syncthreads();                               // all mma/exp done
    if (tig == 0) {
        #pragma unroll
        for (int mt = 0; mt < 2; mt++) {
            sRed[(warp & 3) * 128 + wm + mt * 16 + gid]     = rs[mt][0];
            sRed[(warp & 3) * 128 + wm + mt * 16 + gid + 8] = rs[mt][1];
        }
    }
    __syncthreads();
    if (tid < 128) {
        float s = sRed[tid] + sRed[128 + tid] + sRed[256 + tid] + sRed[384 + tid];
        g_inv[(size_t)bh * S_ + i0 + tid] = 1.0f / s;
    }
    __syncthreads();
}

// ---------------------------------------------------------------------------
// CTX+PROBS PASS: job = (bh, i0). Q resident; loop 16 K/V-tiles (64 wide);
// recompute scores -> exp -> probs = e*inv -> write fp32 probs to attn_out,
// bf16 probs to sP -> P@V mma accumulates ctx.
// smem: sQ @0 (8704), sK @8704 (4352), sV bf16 @13056 (2304 fl),
//       sP bf16 @15360 (4608 fl), sInv @19968 (128), sMask @20096 (64)
// ---------------------------------------------------------------------------
__device__ void ctx_probs_pass(int job, const float* __restrict__ mask,
                               float* __restrict__ attn_out, float* smem) {
    float* sQ = smem;
    float* sK = smem + 8704;
    __nv_bfloat16* sV = (__nv_bfloat16*)(smem + 13056);
    __nv_bfloat16* sP = (__nv_bfloat16*)(smem + 15360);
    float* sInv = smem + 19968;
    float* sMask = smem + 20096;

    const int bh = job >> 3;
    const int i0 = (job & 7) * 128;
    const int b  = bh / 12, h = bh % 12;
    const float* qb = g_q + (size_t)b * S_ * 768 + h * 64;
    const float* kb = g_k + (size_t)b * S_ * 768 + h * 64;
    const float* vb = g_v + (size_t)b * S_ * 768 + h * 64;

    const int tid  = threadIdx.x;
    const int warp = tid >> 5, lane = tid & 31;
    const int gid  = lane >> 2, tig = lane & 3;
    const int wm   = (warp >> 2) * 32;
    const int wn16 = (warp & 3) * 16;

    const int mat = lane >> 3, r8 = lane & 7;
    const int lb  = lane & 15;
    // score: A from sQ (tf32), B from sK (tf32)
    const unsigned adrQA0 = smem_u32(sQ) +
        (((wm + (mat & 1) * 8 + r8) * 68 + (mat >> 1) * 4) << 2);
    const unsigned adrQA1 = adrQA0 + (16 * 68 << 2);
    const unsigned adrKB0 = smem_u32(sK) +
        (((wn16 + (lb & 7)) * 68 + ((lb >> 3) & 1) * 4) << 2);
    // ctx: A from sP (bf16), B from sV (bf16)
    const unsigned adrPA0 = smem_u32(sP) +
        (wm + (mat & 1) * 8 + r8) * 144 + (mat >> 1) * 16;
    const unsigned adrPA1 = adrPA0 + 16 * 144;
    const unsigned adrVB0 = smem_u32(sV) +
        (wn16 + (lb & 7)) * 144 + ((lb >> 3) & 1) * 16;

    // Fill Q tile once; load inv
    #pragma unroll
    for (int e = 0; e < 4; e++) {
        int idx = e * NTHR + tid;
        int m = idx >> 4, d = (idx & 15) * 4;
        *(float4*)&sQ[m * 68 + d] =
            tf32r4(*(const float4*)&qb[(size_t)(i0 + m) * 768 + d]);
    }
    if (tid < 128) sInv[tid] = g_inv[(size_t)bh * S_ + i0 + tid];

    float accC[2][2][4] = {};

    for (int jt = 0; jt < 16; jt++) {
        int jb = jt * 64;
        __syncthreads();                           // guard sK/sV/sP overwrite
        #pragma unroll
        for (int e = 0; e < 2; e++) {
            int idx = e * NTHR + tid;              // 0..1023
            int m = idx >> 4, d = (idx & 15) * 4;
            *(float4*)&sK[m * 68 + d] =
                tf32r4(*(const float4*)&kb[(size_t)(jb + m) * 768 + d]);
        }
        {
            int n  = tid & 63;
            int kg = (tid >> 6) * 8;
            float w[8];
            #pragma unroll
            for (int i = 0; i < 8; i++)
                w[i] = vb[(size_t)(jb + kg + i) * 768 + n];
            uint4 u = {bf2(w[0], w[1]), bf2(w[2], w[3]),
                       bf2(w[4], w[5]), bf2(w[6], w[7])};
            *(uint4*)&sV[n * 72 + kg] = u;
        }
        if (tid < 64) sMask[tid] = mask[(size_t)b * S_ + jb + tid];
        __syncthreads();

        // score mma (m128 x n64, k64)
        float accS[2][2][4] = {};
        #pragma unroll
        for (int ks = 0; ks < 64; ks += 8) {
            const unsigned boff = ks << 2;
            unsigned b0[2], b1[2];
            #pragma unroll
            for (int nt = 0; nt < 2; nt++)
                ldsm_x2(b0[nt], b1[nt], adrKB0 + nt * (8 * 68 << 2) + boff);
            #pragma unroll
            for (int mt = 0; mt < 2; mt++) {
                unsigned a0, a1, a2, a3;
                ldsm_x4(a0, a1, a2, a3, (mt ? adrQA1 : adrQA0) + boff);
                #pragma unroll
                for (int nt = 0; nt < 2; nt++)
                    mma_tf32(accS[mt][nt], a0, a1, a2, a3, b0[nt], b1[nt]);
            }
        }

        // exp -> probs -> attn_out (fp32) + sP (bf16)
        #pragma unroll
        for (int mt = 0; mt < 2; mt++) {
            int rl0 = wm + mt * 16 + gid;
            float iv0 = sInv[rl0], iv1 = sInv[rl0 + 8];
            #pragma unroll
            for (int nt = 0; nt < 2; nt++) {
                int lc = wn16 + nt * 8 + tig * 2;
                float mk0 = (1.0f - sMask[lc])     * -10000.0f;
                float mk1 = (1.0f - sMask[lc + 1]) * -10000.0f;
                float p0 = __expf(accS[mt][nt][0] * 0.125f + mk0) * iv0;
                float p1 = __expf(accS[mt][nt][1] * 0.125f + mk1) * iv0;
                float p2 = __expf(accS[mt][nt][2] * 0.125f + mk0) * iv1;
                float p3 = __expf(accS[mt][nt][3] * 0.125f + mk1) * iv1;
                *(unsigned*)&sP[rl0 * 72 + lc]       = bf2(p0, p1);
                *(unsigned*)&sP[(rl0 + 8) * 72 + lc] = bf2(p2, p3);
                if (attn_out) {
                    size_t ob = (size_t)bh * S_ * S_ + jb + lc;
                    float2 q0 = {p0, p1};
                    float2 q1 = {p2, p3};
                    *(float2*)&attn_out[ob + (size_t)(i0 + rl0) * S_]     = q0;
                    *(float2*)&attn_out[ob + (size_t)(i0 + rl0 + 8) * S_] = q1;
                }
            }
        }
        __syncthreads();                           // sP ready for all warps

        // ctx mma: P (m128 x k64) @ V (k64 x n64), warp tile 32x16
        #pragma unroll
        for (int ks = 0; ks < 64; ks += 16) {
            const unsigned boff = ks << 1;
            unsigned b0[2], b1[2];
            #pragma unroll
            for (int nt = 0; nt < 2; nt++)
                ldsm_x2(b0[nt], b1[nt], adrVB0 + nt * (8 * 144) + boff);
            #pragma unroll
            for (int mt = 0; mt < 2; mt++) {
                unsigned a0, a1, a2, a3;
                ldsm_x4(a0, a1, a2, a3, (mt ? adrPA1 : adrPA0) + boff);
                #pragma unroll
                for (int nt = 0; nt < 2; nt++)
                    mma_bf16(accC[mt][nt], a0, a1, a2, a3, b0[nt], b1[nt]);
            }
        }
    }

    // epilogue: ctx already normalized (probs were normalized before mma)
    #pragma unroll
    for (int mt = 0; mt < 2; mt++) {
        int s = i0 + wm + mt * 16 + gid;
        #pragma unroll
        for (int nt = 0; nt < 2; nt++) {
            int c = h * 64 + wn16 + nt * 8 + tig * 2;
            float2 v0 = {accC[mt][nt][0], accC[mt][nt][1]};
            float2 v1 = {accC[mt][nt][2], accC[mt][nt][3]};
            *(float2*)&g_ctx[(size_t)(b * S_ + s) * 768 + c]     = v0;
            *(float2*)&g_ctx[(size_t)(b * S_ + s + 8) * 768 + c] = v1;
        }
    }
    __syncthreads();
}

// ---------------------------------------------------------------------------
// The single fused kernel.
// ---------------------------------------------------------------------------
__global__ __launch_bounds__(NTHR, 2)
void fused_kernel(const float* __restrict__ query, const float* __restrict__ key,
                  const float* __restrict__ value, const float* __restrict__ mask,
                  const float* __restrict__ Wq, const float* __restrict__ bq,
                  const float* __restrict__ Wk, const float* __restrict__ bk,
                  const float* __restrict__ Wv, const float* __restrict__ bv,
                  const float* __restrict__ Wo, const float* __restrict__ bo,
                  const float* __restrict__ gamma, const float* __restrict__ beta,
                  float* __restrict__ out, float* __restrict__ attn_out) {
    extern __shared__ float smem[];
    const int tid  = threadIdx.x;
    const int warp = tid >> 5, lane = tid & 31;

    // ---- Phase 1: QKV projections (1152 jobs, tf32) ----
    for (int job = blockIdx.x; job < 3 * 384; job += NBLK) {
        int which = job / 384;
        int t = job % 384;
        const float* A  = (which == 0) ? query : (which == 1) ? key : value;
        const float* W  = (which == 0) ? Wq    : (which == 1) ? Wk  : Wv;
        const float* bb = (which == 0) ? bq    : (which == 1) ? bk  : bv;
        float* O        = (which == 0) ? g_q   : (which == 1) ? g_k : g_v;
        gemm_tile_tf32(A, W, bb, O, t, smem, smem + 8704);
    }
    grid_barrier();

    // ---- Phase 2: sum pass (768 jobs) — row sums only, no E stored ----
    for (int job = blockIdx.x; job < 768; job += NBLK)
        sum_pass(job, mask, smem);
    grid_barrier();

    // ---- Phase 3: ctx + probs pass (768 jobs) ----
    for (int job = blockIdx.x; job < 768; job += NBLK)
        ctx_probs_pass(job, mask, attn_out, smem);
    grid_barrier();

    // ---- Phase 4: output projection (768 jobs, bf16, 64x128 tiles) ----
    for (int t = blockIdx.x; t < 768; t += NBLK)
        gemm_tile_bf16(g_ctx, Wo, bo, g_proj, t, smem);
    grid_barrier();

    // ---- Phase 5: residual + LayerNorm — warp per row ----
    for (int row = blockIdx.x * 16 + warp; row < MROWS; row += NBLK * 16) {
        const float* pp = g_proj + (size_t)row * 768;
        const float* op = query + (size_t)row * 768;

        float4 x[6];
        float sum = 0.0f;
        #pragma unroll
        for (int v = 0; v < 6; v++) {
            int off = v * 128 + lane * 4;
            float4 a = *(const float4*)&pp[off];
            float4 o = *(const float4*)&op[off];
            x[v].x = a.x + o.x; x[v].y = a.y + o.y;
            x[v].z = a.z + o.z; x[v].w = a.w + o.w;
            sum += x[v].x + x[v].y + x[v].z + x[v].w;
        }
        #pragma unroll
        for (int o = 16; o > 0; o >>= 1)
            sum += __shfl_xor_sync(0xFFFFFFFFu, sum, o);
        const float mu = sum * (1.0f / 768.0f);

        float var = 0.0f;
        #pragma unroll
        for (int v = 0; v < 6; v++) {
            float dx = x[v].x - mu, dy = x[v].y - mu;
            float dz = x[v].z - mu, dw = x[v].w - mu;
            var += dx * dx + dy * dy + dz * dz + dw * dw;
        }
        #pragma unroll
        for (int o = 16; o > 0; o >>= 1)
            var += __shfl_xor_sync(0xFFFFFFFFu, var, o);
        const float inv = rsqrtf(var * (1.0f / 768.0f) + 1e-8f);

        #pragma unroll
        for (int v = 0; v < 6; v++) {
            int off = v * 128 + lane * 4;
            float4 g = *(const float4*)&gamma[off];
            float4 bt = *(const float4*)&beta[off];
            float4 r;
            r.x = (x[v].x - mu) * inv * g.x + bt.x;
            r.y = (x[v].y - mu) * inv * g.y + bt.y;
            r.z = (x[v].z - mu) * inv * g.z + bt.z;
            r.w = (x[v].w - mu) * inv * g.w + bt.w;
            *(float4*)&out[(size_t)row * 768 + off] = r;
        }
    }
}

// ---------------------------------------------------------------------------
// Launch
// ---------------------------------------------------------------------------
extern "C" void kernel_launch(void* const* d_in, const int* in_sizes, int n_in,
                              void* d_out, int out_size) {
    const float* big[3]  = {0, 0, 0};
    const float* mats[4] = {0, 0, 0, 0};
    const float* vecs[6] = {0, 0, 0, 0, 0, 0};
    const float* mask = 0;
    int nb = 0, nm = 0, nv = 0;
    for (int i = 0; i < n_in; i++) {
        const float* p = (const float*)d_in[i];
        switch (in_sizes[i]) {
            case 6291456: if (nb < 3) big[nb++] = p;  break;
            case 589824:  if (nm < 4) mats[nm++] = p; break;
            case 768:     if (nv < 6) vecs[nv++] = p; break;
            case 8192:    mask = p;                   break;
            default: break;
        }
    }
    float* out = (float*)d_out;
    float* attn_out = ((long long)out_size >= (long long)BSD + BHSS)
                          ? (out + BSD) : 0;

    cudaFuncSetAttribute(fused_kernel,
                         cudaFuncAttributeMaxDynamicSharedMemorySize, DYN_SMEM);

    fused_kernel<<<NBLK, NTHR, DYN_SMEM>>>(big[0], big[1], big[2], mask,
                                           mats[0], vecs[0], mats[1], vecs[1],
                                           mats[2], vecs[2], mats[3], vecs[3],
                                           vecs[4], vecs[5], out, attn_out);
}

// round 15
// speedup vs baseline: 1.1234x; 1.0347x over previous
#include <cuda_runtime.h>
#include <cuda_bf16.h>

// Problem constants
#define B_    8
#define S_    1024
#define MROWS 8192                    // B*S
#define BSD   6291456                 // MROWS*D
#define BHSS  100663296LL             // B*H*S*S

#define NBLK  296                     // 2 per SM x 148 SMs, co-resident
#define NTHR  512
#define DYN_SMEM 107520               // ctx pass high-water: 26880 floats

// Device-global scratch — used ONLY within a single kernel launch.
__device__ float g_q[BSD];                 // tf32-RNA-rounded fp32
__device__ float g_k[BSD];                 // tf32-RNA-rounded fp32
__device__ __nv_bfloat16 g_v16[BSD];       // V projection, bf16
__device__ __nv_bfloat16 g_ctx16[BSD];     // context, bf16
__device__ __nv_bfloat16 g_wo16[589824];   // Wo converted to bf16
__device__ float g_proj[BSD];
__device__ float g_inv[98304];             // per-row 1/sum

// Software grid barrier (generation counter; replay-safe).
__device__ unsigned g_bar_count;
__device__ unsigned g_bar_gen;

__device__ __forceinline__ void grid_barrier() {
    __syncthreads();
    if (threadIdx.x == 0) {
        __threadfence();
        unsigned gen = g_bar_gen;
        unsigned old = atomicAdd(&g_bar_count, 1u);
        if (old == (unsigned)(gridDim.x - 1)) {
            g_bar_count = 0;
            __threadfence();
            atomicAdd(&g_bar_gen, 1u);
        } else {
            while (atomicAdd(&g_bar_gen, 0u) == gen) { __nanosleep(64); }
        }
        __threadfence();
    }
    __syncthreads();
}

__device__ __forceinline__ float tf32r(float x) {
    unsigned u;
    asm("cvt.rna.tf32.f32 %0, %1;" : "=r"(u) : "f"(x));
    return __uint_as_float(u);
}
__device__ __forceinline__ unsigned bf2(float a, float b) {
    __nv_bfloat162 h = __floats2bfloat162_rn(a, b);
    return *(unsigned*)&h;
}

__device__ __forceinline__ void cpa16(unsigned dst, const void* src) {
    asm volatile("cp.async.cg.shared.global [%0], [%1], 16;"
                 :: "r"(dst), "l"(src));
}
__device__ __forceinline__ void cp_commit() {
    asm volatile("cp.async.commit_group;" ::: "memory");
}
__device__ __forceinline__ void cp_wait0() {
    asm volatile("cp.async.wait_group 0;" ::: "memory");
}

__device__ __forceinline__ void mma_tf32(float* acc, unsigned a0, unsigned a1,
                                         unsigned a2, unsigned a3,
                                         unsigned b0, unsigned b1) {
    asm volatile(
        "mma.sync.aligned.m16n8k8.row.col.f32.tf32.tf32.f32 "
        "{%0,%1,%2,%3}, {%4,%5,%6,%7}, {%8,%9}, {%0,%1,%2,%3};"
        : "+f"(acc[0]), "+f"(acc[1]), "+f"(acc[2]), "+f"(acc[3])
        : "r"(a0), "r"(a1), "r"(a2), "r"(a3), "r"(b0), "r"(b1));
}
__device__ __forceinline__ void mma_bf16(float* acc, unsigned a0, unsigned a1,
                                         unsigned a2, unsigned a3,
                                         unsigned b0, unsigned b1) {
    asm volatile(
        "mma.sync.aligned.m16n8k16.row.col.f32.bf16.bf16.f32 "
        "{%0,%1,%2,%3}, {%4,%5,%6,%7}, {%8,%9}, {%0,%1,%2,%3};"
        : "+f"(acc[0]), "+f"(acc[1]), "+f"(acc[2]), "+f"(acc[3])
        : "r"(a0), "r"(a1), "r"(a2), "r"(a3), "r"(b0), "r"(b1));
}
__device__ __forceinline__ void ldsm_x4(unsigned& r0, unsigned& r1,
                                        unsigned& r2, unsigned& r3,
                                        unsigned addr) {
    asm volatile("ldmatrix.sync.aligned.m8n8.x4.shared.b16 {%0,%1,%2,%3}, [%4];"
                 : "=r"(r0), "=r"(r1), "=r"(r2), "=r"(r3) : "r"(addr));
}
__device__ __forceinline__ void ldsm_x2(unsigned& r0, unsigned& r1,
                                        unsigned addr) {
    asm volatile("ldmatrix.sync.aligned.m8n8.x2.shared.b16 {%0,%1}, [%2];"
                 : "=r"(r0), "=r"(r1) : "r"(addr));
}
__device__ __forceinline__ void ldsm_x2t(unsigned& r0, unsigned& r1,
                                         unsigned addr) {
    asm volatile("ldmatrix.sync.aligned.m8n8.x2.trans.shared.b16 {%0,%1}, [%2];"
                 : "=r"(r0), "=r"(r1) : "r"(addr));
}
__device__ __forceinline__ unsigned smem_u32(const void* p) {
    return (unsigned)__cvta_generic_to_shared(p);
}

// ---------------------------------------------------------------------------
// Phase 1: 128x128 tf32 GEMM tile, BK=64 (QKV projections).
// Q,K outputs tf32-RNA-rounded fp32; V output bf16 (out16 != null).
// ---------------------------------------------------------------------------
__device__ void qkv_tile(const float* __restrict__ A, const float* __restrict__ W,
                         const float* __restrict__ bias,
                         float* __restrict__ outF, __nv_bfloat16* __restrict__ out16,
                         int tileIdx, float* sA, float* sB) {
    const int row0 = (tileIdx / 6) * 128;
    const int col0 = (tileIdx % 6) * 128;
    const int tid  = threadIdx.x;
    const int warp = tid >> 5, lane = tid & 31;
    const int gid  = lane >> 2, tig = lane & 3;
    const int wm   = (warp >> 2) * 32, wn = (warp & 3) * 32;

    const int mat = lane >> 3, r8 = lane & 7;
    const int lb  = lane & 15;
    const unsigned adrA0 = smem_u32(sA) +
        (((wm + (mat & 1) * 8 + r8) * 68 + (mat >> 1) * 4) << 2);
    const unsigned adrA1 = adrA0 + (16 * 68 << 2);
    const unsigned adrB0 = smem_u32(sB) +
        (((wn + (lb & 7)) * 68 + ((lb >> 3) & 1) * 4) << 2);

    float acc[2][4][4] = {};

    for (int k0 = 0; k0 < 768; k0 += 64) {
        #pragma unroll
        for (int e = 0; e < 4; e++) {
            int idx = (e * NTHR + tid) * 4;
            int m = idx >> 6, k = idx & 63;
            float4 v = *(const float4*)&A[(size_t)(row0 + m) * 768 + k0 + k];
            v.x = tf32r(v.x); v.y = tf32r(v.y); v.z = tf32r(v.z); v.w = tf32r(v.w);
            *(float4*)&sA[m * 68 + k] = v;
        }
        {
            int n  = tid & 127;
            int kg = (tid >> 7) * 16;
            #pragma unroll
            for (int g = 0; g < 4; g++) {
                sB[n * 68 + kg + g * 4 + 0] = tf32r(W[(size_t)(k0 + kg + g * 4 + 0) * 768 + col0 + n]);
                sB[n * 68 + kg + g * 4 + 1] = tf32r(W[(size_t)(k0 + kg + g * 4 + 1) * 768 + col0 + n]);
                sB[n * 68 + kg + g * 4 + 2] = tf32r(W[(size_t)(k0 + kg + g * 4 + 2) * 768 + col0 + n]);
                sB[n * 68 + kg + g * 4 + 3] = tf32r(W[(size_t)(k0 + kg + g * 4 + 3) * 768 + col0 + n]);
            }
        }
        __syncthreads();

        #pragma unroll
        for (int ks = 0; ks < 64; ks += 8) {
            const unsigned boff = ks << 2;
            unsigned b0[4], b1[4];
            #pragma unroll
            for (int nt = 0; nt < 4; nt++)
                ldsm_x2(b0[nt], b1[nt], adrB0 + nt * (8 * 68 << 2) + boff);
            #pragma unroll
            for (int mt = 0; mt < 2; mt++) {
                unsigned a0, a1, a2, a3;
                ldsm_x4(a0, a1, a2, a3, (mt ? adrA1 : adrA0) + boff);
                #pragma unroll
                for (int nt = 0; nt < 4; nt++)
                    mma_tf32(acc[mt][nt], a0, a1, a2, a3, b0[nt], b1[nt]);
            }
        }
        __syncthreads();
    }

    #pragma unroll
    for (int mt = 0; mt < 2; mt++) {
        int r = row0 + wm + mt * 16 + gid;
        #pragma unroll
        for (int nt = 0; nt < 4; nt++) {
            int c = col0 + wn + nt * 8 + tig * 2;
            float v00 = acc[mt][nt][0] + bias[c];
            float v01 = acc[mt][nt][1] + bias[c + 1];
            float v10 = acc[mt][nt][2] + bias[c];
            float v11 = acc[mt][nt][3] + bias[c + 1];
            if (out16) {
                *(unsigned*)&out16[(size_t)r * 768 + c]       = bf2(v00, v01);
                *(unsigned*)&out16[(size_t)(r + 8) * 768 + c] = bf2(v10, v11);
            } else {
                float2 w0 = {tf32r(v00), tf32r(v01)};
                float2 w1 = {tf32r(v10), tf32r(v11)};
                *(float2*)&outF[(size_t)r * 768 + c]       = w0;
                *(float2*)&outF[(size_t)(r + 8) * 768 + c] = w1;
            }
        }
    }
}

// ---------------------------------------------------------------------------
// SUM PASS: job=(bh,i0). Q resident (cp.async); 16 j-tiles of 64,
// double-buffered raw cp.async K fills; exp row sums -> g_inv.
// smem: sQ @0 (8704), sK @8704 (2x4352), sMask @17408 (2x64), sRed @17536 (512)
// ---------------------------------------------------------------------------
__device__ void sum_pass(int job, const float* __restrict__ mask, float* smem) {
    float* sQ = smem;
    float* sK = smem + 8704;
    float* sMask = smem + 17408;
    float* sRed = smem + 17536;

    const int bh = job >> 3;
    const int i0 = (job & 7) * 128;
    const int b  = bh / 12, h = bh % 12;
    const float* qb = g_q + (size_t)b * S_ * 768 + h * 64;
    const float* kb = g_k + (size_t)b * S_ * 768 + h * 64;

    const int tid  = threadIdx.x;
    const int warp = tid >> 5, lane = tid & 31;
    const int gid  = lane >> 2, tig = lane & 3;
    const int wm   = (warp >> 2) * 32;
    const int wn16 = (warp & 3) * 16;

    const int mat = lane >> 3, r8 = lane & 7;
    const int lb  = lane & 15;
    const unsigned adrQ0 = smem_u32(sQ) +
        (((wm + (mat & 1) * 8 + r8) * 68 + (mat >> 1) * 4) << 2);
    const unsigned adrQ1 = adrQ0 + (16 * 68 << 2);
    const unsigned adrKb = smem_u32(sK) +
        (((wn16 + (lb & 7)) * 68 + ((lb >> 3) & 1) * 4) << 2);

    const unsigned sQu = smem_u32(sQ);
    const unsigned sKu = smem_u32(sK);
    const unsigned sMu = smem_u32(sMask);

    // prologue: Q + K tile 0 + mask 0 (raw copies; g_q/g_k pre-rounded)
    #pragma unroll
    for (int e = 0; e < 4; e++) {
        int idx = e * NTHR + tid;
        int m = idx >> 4, d = (idx & 15) * 4;
        cpa16(sQu + (unsigned)(m * 68 + d) * 4, &qb[(size_t)(i0 + m) * 768 + d]);
    }
    {
        int j = tid >> 4, d = (tid & 15) * 4;
        cpa16(sKu + (unsigned)(j * 68 + d) * 4, &kb[(size_t)j * 768 + d]);
        int idx = NTHR + tid;
        j = idx >> 4; d = (idx & 15) * 4;
        cpa16(sKu + (unsigned)(j * 68 + d) * 4, &kb[(size_t)j * 768 + d]);
    }
    if (tid < 16) cpa16(sMu + tid * 16, &mask[(size_t)b * S_ + tid * 4]);
    cp_commit();

    float rs[2][2] = {};

    for (int jt = 0; jt < 16; jt++) {
        cp_wait0();
        __syncthreads();
        int cur = jt & 1, nxt = cur ^ 1;
        if (jt + 1 < 16) {
            int jb2 = (jt + 1) * 64;
            #pragma unroll
            for (int e = 0; e < 2; e++) {
                int idx = e * NTHR + tid;
                int j = idx >> 4, d = (idx & 15) * 4;
                cpa16(sKu + (unsigned)(nxt * 4352 + j * 68 + d) * 4,
                      &kb[(size_t)(jb2 + j) * 768 + d]);
            }
            if (tid < 16)
                cpa16(sMu + (unsigned)(nxt * 64 + tid * 4) * 4,
                      &mask[(size_t)b * S_ + jb2 + tid * 4]);
            cp_commit();
        }

        const unsigned aK = adrKb + (unsigned)cur * 4352 * 4;
        float accS[2][2][4] = {};
        #pragma unroll
        for (int ks = 0; ks < 64; ks += 8) {
            const unsigned boff = ks << 2;
            unsigned b0[2], b1[2];
            #pragma unroll
            for (int nt = 0; nt < 2; nt++)
                ldsm_x2(b0[nt], b1[nt], aK + nt * (8 * 68 << 2) + boff);
            #pragma unroll
            for (int mt = 0; mt < 2; mt++) {
                unsigned a0, a1, a2, a3;
                ldsm_x4(a0, a1, a2, a3, (mt ? adrQ1 : adrQ0) + boff);
                #pragma unroll
                for (int nt = 0; nt < 2; nt++)
                    mma_tf32(accS[mt][nt], a0, a1, a2, a3, b0[nt], b1[nt]);
            }
        }

        const float* mk = sMask + cur * 64;
        #pragma unroll
        for (int mt = 0; mt < 2; mt++) {
            #pragma unroll
            for (int nt = 0; nt < 2; nt++) {
                int lc = wn16 + nt * 8 + tig * 2;
                float mk0 = (1.0f - mk[lc])     * -10000.0f;
                float mk1 = (1.0f - mk[lc + 1]) * -10000.0f;
                rs[mt][0] += __expf(accS[mt][nt][0] * 0.125f + mk0)
                           + __expf(accS[mt][nt][1] * 0.125f + mk1);
                rs[mt][1] += __expf(accS[mt][nt][2] * 0.125f + mk0)
                           + __expf(accS[mt][nt][3] * 0.125f + mk1);
            }
        }
    }

    #pragma unroll
    for (int o = 1; o < 4; o <<= 1) {
        rs[0][0] += __shfl_xor_sync(0xFFFFFFFFu, rs[0][0], o);
        rs[0][1] += __shfl_xor_sync(0xFFFFFFFFu, rs[0][1], o);
        rs[1][0] += __shfl_xor_sync(0xFFFFFFFFu, rs[1][0], o);
        rs[1][1] += __shfl_xor_sync(0xFFFFFFFFu, rs[1][1], o);
    }
    __syncthreads();
    if (tig == 0) {
        #pragma unroll
        for (int mt = 0; mt < 2; mt++) {
            sRed[(warp & 3) * 128 + wm + mt * 16 + gid]     = rs[mt][0];
            sRed[(warp & 3) * 128 + wm + mt * 16 + gid + 8] = rs[mt][1];
        }
    }
    __syncthreads();
    if (tid < 128) {
        float s = sRed[tid] + sRed[128 + tid] + sRed[256 + tid] + sRed[384 + tid];
        g_inv[(size_t)bh * S_ + i0 + tid] = 1.0f / s;
    }
    __syncthreads();
}

// ---------------------------------------------------------------------------
// CTX+PROBS PASS: job=(bh,i0). Q resident; 16 j-tiles of 64, double-buffered
// raw cp.async K (tf32) + V (bf16, [j][d], consumed via ldmatrix.trans).
// Recompute scores -> probs -> attn_out (fp32) + sP (bf16) -> P@V -> g_ctx16.
// smem (floats): sQ @0 (8704) | sK @8704 (2x4352) | sV @17408 (2x2304)
//              | sP @22016 (4608) | sInv @26624 (128) | sMask @26752 (2x64)
// total = 26880 floats = 107520 bytes = DYN_SMEM
// V buffer stride = 2304 floats = 9216 BYTES (64 rows x 144 B).
// ---------------------------------------------------------------------------
__device__ void ctx_probs_pass(int job, const float* __restrict__ mask,
                               float* __restrict__ attn_out, float* smem) {
    float* sQ = smem;
    float* sK = smem + 8704;
    __nv_bfloat16* sV = (__nv_bfloat16*)(smem + 17408);
    __nv_bfloat16* sP = (__nv_bfloat16*)(smem + 22016);
    float* sInv = smem + 26624;
    float* sMask = smem + 26752;

    const int bh = job >> 3;
    const int i0 = (job & 7) * 128;
    const int b  = bh / 12, h = bh % 12;
    const float* qb = g_q + (size_t)b * S_ * 768 + h * 64;
    const float* kb = g_k + (size_t)b * S_ * 768 + h * 64;
    const __nv_bfloat16* vb = g_v16 + (size_t)b * S_ * 768 + h * 64;

    const int tid  = threadIdx.x;
    const int warp = tid >> 5, lane = tid & 31;
    const int gid  = lane >> 2, tig = lane & 3;
    const int wm   = (warp >> 2) * 32;
    const int wn16 = (warp & 3) * 16;

    const int mat = lane >> 3, r8 = lane & 7;
    const int lb  = lane & 15;
    const unsigned adrQ0 = smem_u32(sQ) +
        (((wm + (mat & 1) * 8 + r8) * 68 + (mat >> 1) * 4) << 2);
    const unsigned adrQ1 = adrQ0 + (16 * 68 << 2);
    const unsigned adrKb = smem_u32(sK) +
        (((wn16 + (lb & 7)) * 68 + ((lb >> 3) & 1) * 4) << 2);
    const unsigned adrPA0 = smem_u32(sP) +
        (wm + (mat & 1) * 8 + r8) * 144 + (mat >> 1) * 16;
    const unsigned adrPA1 = adrPA0 + 16 * 144;
    // V trans fragment: lane lb selects source k-row within the 16-row slab
    const unsigned adrVb = smem_u32(sV) + lb * 144 + wn16 * 2;

    const unsigned sQu = smem_u32(sQ);
    const unsigned sKu = smem_u32(sK);
    const unsigned sVu = smem_u32(sV);
    const unsigned sMu = smem_u32(sMask);

    // prologue: Q + K0 + V0 + mask0 (raw byte copies)
    #pragma unroll
    for (int e = 0; e < 4; e++) {
        int idx = e * NTHR + tid;
        int m = idx >> 4, d = (idx & 15) * 4;
        cpa16(sQu + (unsigned)(m * 68 + d) * 4, &qb[(size_t)(i0 + m) * 768 + d]);
    }
    #pragma unroll
    for (int e = 0; e < 2; e++) {
        int idx = e * NTHR + tid;
        int j = idx >> 4, d = (idx & 15) * 4;
        cpa16(sKu + (unsigned)(j * 68 + d) * 4, &kb[(size_t)j * 768 + d]);
    }
    {
        int j = tid >> 3, c = (tid & 7) * 8;       // 64 rows x 8 chunks of 8 b16
        cpa16(sVu + (unsigned)(j * 144 + c * 2), &vb[(size_t)j * 768 + c]);
    }
    if (tid < 16) cpa16(sMu + tid * 16, &mask[(size_t)b * S_ + tid * 4]);
    cp_commit();
    if (tid < 128) sInv[tid] = g_inv[(size_t)bh * S_ + i0 + tid];

    float accC[2][2][4] = {};

    for (int jt = 0; jt < 16; jt++) {
        cp_wait0();
        __syncthreads();
        int cur = jt & 1, nxt = cur ^ 1;
        int jb = jt * 64;
        if (jt + 1 < 16) {
            int jb2 = jb + 64;
            #pragma unroll
            for (int e = 0; e < 2; e++) {
                int idx = e * NTHR + tid;
                int j = idx >> 4, d = (idx & 15) * 4;
                cpa16(sKu + (unsigned)(nxt * 4352 + j * 68 + d) * 4,
                      &kb[(size_t)(jb2 + j) * 768 + d]);
            }
            {
                int j = tid >> 3, c = (tid & 7) * 8;
                cpa16(sVu + (unsigned)(nxt * 9216 + j * 144 + c * 2),
                      &vb[(size_t)(jb2 + j) * 768 + c]);
            }
            if (tid < 16)
                cpa16(sMu + (unsigned)(nxt * 64 + tid * 4) * 4,
                      &mask[(size_t)b * S_ + jb2 + tid * 4]);
            cp_commit();
        }

        // score mma on current K buffer (m128 x n64, k64)
        const unsigned aK = adrKb + (unsigned)cur * 4352 * 4;
        float accS[2][2][4] = {};
        #pragma unroll
        for (int ks = 0; ks < 64; ks += 8) {
            const unsigned boff = ks << 2;
            unsigned b0[2], b1[2];
            #pragma unroll
            for (int nt = 0; nt < 2; nt++)
                ldsm_x2(b0[nt], b1[nt], aK + nt * (8 * 68 << 2) + boff);
            #pragma unroll
            for (int mt = 0; mt < 2; mt++) {
                unsigned a0, a1, a2, a3;
                ldsm_x4(a0, a1, a2, a3, (mt ? adrQ1 : adrQ0) + boff);
                #pragma unroll
                for (int nt = 0; nt < 2; nt++)
                    mma_tf32(accS[mt][nt], a0, a1, a2, a3, b0[nt], b1[nt]);
            }
        }

        // exp -> probs -> attn_out (fp32) + sP (bf16)
        const float* mk = sMask + cur * 64;
        #pragma unroll
        for (int mt = 0; mt < 2; mt++) {
            int rl0 = wm + mt * 16 + gid;
            float iv0 = sInv[rl0], iv1 = sInv[rl0 + 8];
            #pragma unroll
            for (int nt = 0; nt < 2; nt++) {
                int lc = wn16 + nt * 8 + tig * 2;
                float mk0 = (1.0f - mk[lc])     * -10000.0f;
                float mk1 = (1.0f - mk[lc + 1]) * -10000.0f;
                float p0 = __expf(accS[mt][nt][0] * 0.125f + mk0) * iv0;
                float p1 = __expf(accS[mt][nt][1] * 0.125f + mk1) * iv0;
                float p2 = __expf(accS[mt][nt][2] * 0.125f + mk0) * iv1;
                float p3 = __expf(accS[mt][nt][3] * 0.125f + mk1) * iv1;
                *(unsigned*)&sP[rl0 * 72 + lc]       = bf2(p0, p1);
                *(unsigned*)&sP[(rl0 + 8) * 72 + lc] = bf2(p2, p3);
                if (attn_out) {
                    size_t ob = (size_t)bh * S_ * S_ + jb + lc;
                    float2 q0 = {p0, p1};
                    float2 q1 = {p2, p3};
                    *(float2*)&attn_out[ob + (size_t)(i0 + rl0) * S_]     = q0;
                    *(float2*)&attn_out[ob + (size_t)(i0 + rl0 + 8) * S_] = q1;
                }
            }
        }
        __syncthreads();   // sP published

        // ctx mma: P (m128 x k64) @ V (k64 x n64), V via ldmatrix.trans
        const unsigned aV = adrVb + (unsigned)cur * 9216;
        #pragma unroll
        for (int ks = 0; ks < 64; ks += 16) {
            unsigned b0[2], b1[2];
            #pragma unroll
            for (int nt = 0; nt < 2; nt++)
                ldsm_x2t(b0[nt], b1[nt], aV + ks * 144 + nt * 16);
            #pragma unroll
            for (int mt = 0; mt < 2; mt++) {
                unsigned a0, a1, a2, a3;
                ldsm_x4(a0, a1, a2, a3, (mt ? adrPA1 : adrPA0) + (ks << 1));
                #pragma unroll
                for (int nt = 0; nt < 2; nt++)
                    mma_bf16(accC[mt][nt], a0, a1, a2, a3, b0[nt], b1[nt]);
            }
        }
    }

    // epilogue: write bf16 context
    #pragma unroll
    for (int mt = 0; mt < 2; mt++) {
        int s = i0 + wm + mt * 16 + gid;
        #pragma unroll
        for (int nt = 0; nt < 2; nt++) {
            int c = h * 64 + wn16 + nt * 8 + tig * 2;
            *(unsigned*)&g_ctx16[(size_t)(b * S_ + s) * 768 + c] =
                bf2(accC[mt][nt][0], accC[mt][nt][1]);
            *(unsigned*)&g_ctx16[(size_t)(b * S_ + s + 8) * 768 + c] =
                bf2(accC[mt][nt][2], accC[mt][nt][3]);
        }
    }
    __syncthreads();   // protect smem before next job's prologue
}

// ---------------------------------------------------------------------------
// O PROJECTION: 64x128 tile, BK=64, bf16, fully raw cp.async double-buffered.
// A = g_ctx16 [m][k]; B = g_wo16 [k][n] via ldmatrix.trans.
// smem (floats): sA16 @0 (2 x 2304) | sB16 @4608 (2 x 4352)  -> 13312 fl
// ---------------------------------------------------------------------------
__device__ void oproj_tile(const float* __restrict__ bias, int tileIdx,
                           float* smem) {
    __nv_bfloat16* sA16 = (__nv_bfloat16*)smem;
    __nv_bfloat16* sB16 = (__nv_bfloat16*)(smem + 4608);

    const int row0 = (tileIdx / 6) * 64;
    const int col0 = (tileIdx % 6) * 128;
    const int tid  = threadIdx.x;
    const int warp = tid >> 5, lane = tid & 31;
    const int gid  = lane >> 2, tig = lane & 3;
    const int wm16 = (warp >> 2) * 16;
    const int wn32 = (warp & 3) * 32;

    const int mat = lane >> 3, r8 = lane & 7;
    const int lb  = lane & 15;
    const unsigned adrA = smem_u32(sA16) +
        (wm16 + (mat & 1) * 8 + r8) * 144 + (mat >> 1) * 16;
    const unsigned adrB = smem_u32(sB16) + lb * 272 + wn32 * 2;

    const unsigned sAu = smem_u32(sA16);
    const unsigned sBu = smem_u32(sB16);

    // prologue: k0 = 0
    {
        int m = tid >> 3, c = (tid & 7) * 8;
        cpa16(sAu + (unsigned)(m * 144 + c * 2),
              &g_ctx16[(size_t)(row0 + m) * 768 + c]);
        #pragma unroll
        for (int e = 0; e < 2; e++) {
            int idx = e * NTHR + tid;
            int k = idx >> 4, n = (idx & 15) * 8;
            cpa16(sBu + (unsigned)(k * 272 + n * 2),
                  &g_wo16[(size_t)k * 768 + col0 + n]);
        }
    }
    cp_commit();

    float acc[4][4] = {};

    for (int s = 0; s < 12; s++) {
        cp_wait0();
        __syncthreads();
        int cur = s & 1, nxt = cur ^ 1;
        if (s + 1 < 12) {
            int k0 = (s + 1) * 64;
            int m = tid >> 3, c = (tid & 7) * 8;
            cpa16(sAu + (unsigned)(nxt * 9216 + m * 144 + c * 2),
                  &g_ctx16[(size_t)(row0 + m) * 768 + k0 + c]);
            #pragma unroll
            for (int e = 0; e < 2; e++) {
                int idx = e * NTHR + tid;
                int k = idx >> 4, n = (idx & 15) * 8;
                cpa16(sBu + (unsigned)(nxt * 17408 + k * 272 + n * 2),
                      &g_wo16[(size_t)(k0 + k) * 768 + col0 + n]);
            }
            cp_commit();
        }

        const unsigned aA = adrA + (unsigned)cur * 9216;
        const unsigned aB = adrB + (unsigned)cur * 17408;
        #pragma unroll
        for (int ks = 0; ks < 64; ks += 16) {
            unsigned b0[4], b1[4];
            #pragma unroll
            for (int nt = 0; nt < 4; nt++)
                ldsm_x2t(b0[nt], b1[nt], aB + ks * 272 + nt * 16);
            unsigned a0, a1, a2, a3;
            ldsm_x4(a0, a1, a2, a3, aA + (ks << 1));
            #pragma unroll
            for (int nt = 0; nt < 4; nt++)
                mma_bf16(acc[nt], a0, a1, a2, a3, b0[nt], b1[nt]);
        }
    }

    {
        int r = row0 + wm16 + gid;
        #pragma unroll
        for (int nt = 0; nt < 4; nt++) {
            int c = col0 + wn32 + nt * 8 + tig * 2;
            float2 v0 = {acc[nt][0] + bias[c], acc[nt][1] + bias[c + 1]};
            float2 v1 = {acc[nt][2] + bias[c], acc[nt][3] + bias[c + 1]};
            *(float2*)&g_proj[(size_t)r * 768 + c]       = v0;
            *(float2*)&g_proj[(size_t)(r + 8) * 768 + c] = v1;
        }
    }
    __syncthreads();
}

// ---------------------------------------------------------------------------
// The single fused kernel.
// ---------------------------------------------------------------------------
__global__ __launch_bounds__(NTHR, 2)
void fused_kernel(const float* __restrict__ query, const float* __restrict__ key,
                  const float* __restrict__ value, const float* __restrict__ mask,
                  const float* __restrict__ Wq, const float* __restrict__ bq,
                  const float* __restrict__ Wk, const float* __restrict__ bk,
                  const float* __restrict__ Wv, const float* __restrict__ bv,
                  const float* __restrict__ Wo, const float* __restrict__ bo,
                  const float* __restrict__ gamma, const float* __restrict__ beta,
                  float* __restrict__ out, float* __restrict__ attn_out) {
    extern __shared__ float smem[];
    const int tid  = threadIdx.x;
    const int warp = tid >> 5, lane = tid & 31;

    // ---- Phase 0: convert Wo -> bf16 (consumed in phase 4, after barriers) --
    for (int i = blockIdx.x * NTHR + tid; i < 147456; i += NBLK * NTHR) {
        float4 w = ((const float4*)Wo)[i];
        uint2 u = {bf2(w.x, w.y), bf2(w.z, w.w)};
        ((uint2*)g_wo16)[i] = u;
    }

    // ---- Phase 1: QKV projections (1152 jobs) ----
    for (int job = blockIdx.x; job < 3 * 384; job += NBLK) {
        int which = job / 384;
        int t = job % 384;
        const float* A  = (which == 0) ? query : (which == 1) ? key : value;
        const float* W  = (which == 0) ? Wq    : (which == 1) ? Wk  : Wv;
        const float* bb = (which == 0) ? bq    : (which == 1) ? bk  : bv;
        float* OF = (which == 0) ? g_q : (which == 1) ? g_k : 0;
        __nv_bfloat16* O16 = (which == 2) ? g_v16 : 0;
        qkv_tile(A, W, bb, OF, O16, t, smem, smem + 8704);
    }
    grid_barrier();

    // ---- Phase 2: sum pass (768 jobs) ----
    for (int job = blockIdx.x; job < 768; job += NBLK)
        sum_pass(job, mask, smem);
    grid_barrier();

    // ---- Phase 3: ctx + probs pass (768 jobs) ----
    for (int job = blockIdx.x; job < 768; job += NBLK)
        ctx_probs_pass(job, mask, attn_out, smem);
    grid_barrier();

    // ---- Phase 4: output projection (768 jobs) ----
    for (int t = blockIdx.x; t < 768; t += NBLK)
        oproj_tile(bo, t, smem);
    grid_barrier();

    // ---- Phase 5: residual + LayerNorm — warp per row ----
    for (int row = blockIdx.x * 16 + warp; row < MROWS; row += NBLK * 16) {
        const float* pp = g_proj + (size_t)row * 768;
        const float* op = query + (size_t)row * 768;

        float4 x[6];
        float sum = 0.0f;
        #pragma unroll
        for (int v = 0; v < 6; v++) {
            int off = v * 128 + lane * 4;
            float4 a = *(const float4*)&pp[off];
            float4 o = *(const float4*)&op[off];
            x[v].x = a.x + o.x; x[v].y = a.y + o.y;
            x[v].z = a.z + o.z; x[v].w = a.w + o.w;
            sum += x[v].x + x[v].y + x[v].z + x[v].w;
        }
        #pragma unroll
        for (int o = 16; o > 0; o >>= 1)
            sum += __shfl_xor_sync(0xFFFFFFFFu, sum, o);
        const float mu = sum * (1.0f / 768.0f);

        float var = 0.0f;
        #pragma unroll
        for (int v = 0; v < 6; v++) {
            float dx = x[v].x - mu, dy = x[v].y - mu;
            float dz = x[v].z - mu, dw = x[v].w - mu;
            var += dx * dx + dy * dy + dz * dz + dw * dw;
        }
        #pragma unroll
        for (int o = 16; o > 0; o >>= 1)
            var += __shfl_xor_sync(0xFFFFFFFFu, var, o);
        const float inv = rsqrtf(var * (1.0f / 768.0f) + 1e-8f);

        #pragma unroll
        for (int v = 0; v < 6; v++) {
            int off = v * 128 + lane * 4;
            float4 g = *(const float4*)&gamma[off];
            float4 bt = *(const float4*)&beta[off];
            float4 r;
            r.x = (x[v].x - mu) * inv * g.x + bt.x;
            r.y = (x[v].y - mu) * inv * g.y + bt.y;
            r.z = (x[v].z - mu) * inv * g.z + bt.z;
            r.w = (x[v].w - mu) * inv * g.w + bt.w;
            *(float4*)&out[(size_t)row * 768 + off] = r;
        }
    }
}

// ---------------------------------------------------------------------------
// Launch
// ---------------------------------------------------------------------------
extern "C" void kernel_launch(void* const* d_in, const int* in_sizes, int n_in,
                              void* d_out, int out_size) {
    const float* big[3]  = {0, 0, 0};
    const float* mats[4] = {0, 0, 0, 0};
    const float* vecs[6] = {0, 0, 0, 0, 0, 0};
    const float* mask = 0;
    int nb = 0, nm = 0, nv = 0;
    for (int i = 0; i < n_in; i++) {
        const float* p = (const float*)d_in[i];
        switch (in_sizes[i]) {
            case 6291456: if (nb < 3) big[nb++] = p;  break;
            case 589824:  if (nm < 4) mats[nm++] = p; break;
            case 768:     if (nv < 6) vecs[nv++] = p; break;
            case 8192:    mask = p;                   break;
            default: break;
        }
    }
    float* out = (float*)d_out;
    float* attn_out = ((long long)out_size >= (long long)BSD + BHSS)
                          ? (out + BSD) : 0;

    cudaFuncSetAttribute(fused_kernel,
                         cudaFuncAttributeMaxDynamicSharedMemorySize, DYN_SMEM);

    fused_kernel<<<NBLK, NTHR, DYN_SMEM>>>(big[0], big[1], big[2], mask,
                                           mats[0], vecs[0], mats[1], vecs[1],
                                           mats[2], vecs[2], mats[3], vecs[3],
                                           vecs[4], vecs[5], out, attn_out);
}

// round 16
// speedup vs baseline: 1.1866x; 1.0563x over previous
#include <cuda_runtime.h>
#include <cuda_bf16.h>

// Problem constants
#define B_    8
#define S_    1024
#define MROWS 8192                    // B*S
#define BSD   6291456                 // MROWS*D
#define BHSS  100663296LL             // B*H*S*S

#define NBLK  296                     // 2 per SM x 148 SMs, co-resident
#define NTHR  512
#define DYN_SMEM 107520               // ctx pass high-water: 26880 floats

// Device-global scratch — used ONLY within a single kernel launch.
__device__ float g_q[BSD];                 // tf32-RNA-rounded fp32 (ctx scores)
__device__ float g_k[BSD];                 // tf32-RNA-rounded fp32 (ctx scores)
__device__ __nv_bfloat16 g_q16[BSD];       // bf16 Q (sum pass)
__device__ __nv_bfloat16 g_k16[BSD];       // bf16 K (sum pass)
__device__ __nv_bfloat16 g_v16[BSD];       // V projection, bf16
__device__ __nv_bfloat16 g_ctx16[BSD];     // context, bf16
__device__ __nv_bfloat16 g_wo16[589824];   // Wo converted to bf16
__device__ float g_proj[BSD];
__device__ float g_inv[98304];             // per-row 1/sum

// Software grid barrier (generation counter; replay-safe).
__device__ unsigned g_bar_count;
__device__ unsigned g_bar_gen;

__device__ __forceinline__ void grid_barrier() {
    __syncthreads();
    if (threadIdx.x == 0) {
        __threadfence();
        unsigned gen = g_bar_gen;
        unsigned old = atomicAdd(&g_bar_count, 1u);
        if (old == (unsigned)(gridDim.x - 1)) {
            g_bar_count = 0;
            __threadfence();
            atomicAdd(&g_bar_gen, 1u);
        } else {
            while (atomicAdd(&g_bar_gen, 0u) == gen) { __nanosleep(64); }
        }
        __threadfence();
    }
    __syncthreads();
}

__device__ __forceinline__ float tf32r(float x) {
    unsigned u;
    asm("cvt.rna.tf32.f32 %0, %1;" : "=r"(u) : "f"(x));
    return __uint_as_float(u);
}
__device__ __forceinline__ unsigned bf2(float a, float b) {
    __nv_bfloat162 h = __floats2bfloat162_rn(a, b);
    return *(unsigned*)&h;
}

__device__ __forceinline__ void cpa16(unsigned dst, const void* src) {
    asm volatile("cp.async.cg.shared.global [%0], [%1], 16;"
                 :: "r"(dst), "l"(src));
}
__device__ __forceinline__ void cp_commit() {
    asm volatile("cp.async.commit_group;" ::: "memory");
}
__device__ __forceinline__ void cp_wait0() {
    asm volatile("cp.async.wait_group 0;" ::: "memory");
}

__device__ __forceinline__ void mma_tf32(float* acc, unsigned a0, unsigned a1,
                                         unsigned a2, unsigned a3,
                                         unsigned b0, unsigned b1) {
    asm volatile(
        "mma.sync.aligned.m16n8k8.row.col.f32.tf32.tf32.f32 "
        "{%0,%1,%2,%3}, {%4,%5,%6,%7}, {%8,%9}, {%0,%1,%2,%3};"
        : "+f"(acc[0]), "+f"(acc[1]), "+f"(acc[2]), "+f"(acc[3])
        : "r"(a0), "r"(a1), "r"(a2), "r"(a3), "r"(b0), "r"(b1));
}
__device__ __forceinline__ void mma_bf16(float* acc, unsigned a0, unsigned a1,
                                         unsigned a2, unsigned a3,
                                         unsigned b0, unsigned b1) {
    asm volatile(
        "mma.sync.aligned.m16n8k16.row.col.f32.bf16.bf16.f32 "
        "{%0,%1,%2,%3}, {%4,%5,%6,%7}, {%8,%9}, {%0,%1,%2,%3};"
        : "+f"(acc[0]), "+f"(acc[1]), "+f"(acc[2]), "+f"(acc[3])
        : "r"(a0), "r"(a1), "r"(a2), "r"(a3), "r"(b0), "r"(b1));
}
__device__ __forceinline__ void ldsm_x4(unsigned& r0, unsigned& r1,
                                        unsigned& r2, unsigned& r3,
                                        unsigned addr) {
    asm volatile("ldmatrix.sync.aligned.m8n8.x4.shared.b16 {%0,%1,%2,%3}, [%4];"
                 : "=r"(r0), "=r"(r1), "=r"(r2), "=r"(r3) : "r"(addr));
}
__device__ __forceinline__ void ldsm_x2(unsigned& r0, unsigned& r1,
                                        unsigned addr) {
    asm volatile("ldmatrix.sync.aligned.m8n8.x2.shared.b16 {%0,%1}, [%2];"
                 : "=r"(r0), "=r"(r1) : "r"(addr));
}
__device__ __forceinline__ void ldsm_x2t(unsigned& r0, unsigned& r1,
                                         unsigned addr) {
    asm volatile("ldmatrix.sync.aligned.m8n8.x2.trans.shared.b16 {%0,%1}, [%2];"
                 : "=r"(r0), "=r"(r1) : "r"(addr));
}
__device__ __forceinline__ unsigned smem_u32(const void* p) {
    return (unsigned)__cvta_generic_to_shared(p);
}

// ---------------------------------------------------------------------------
// Phase 1: 128x128 tf32 GEMM tile, BK=64 (QKV projections).
// outF: tf32-RNA-rounded fp32 (Q,K). out16: bf16 copy (Q,K,V).
// ---------------------------------------------------------------------------
__device__ void qkv_tile(const float* __restrict__ A, const float* __restrict__ W,
                         const float* __restrict__ bias,
                         float* __restrict__ outF, __nv_bfloat16* __restrict__ out16,
                         int tileIdx, float* sA, float* sB) {
    const int row0 = (tileIdx / 6) * 128;
    const int col0 = (tileIdx % 6) * 128;
    const int tid  = threadIdx.x;
    const int warp = tid >> 5, lane = tid & 31;
    const int gid  = lane >> 2, tig = lane & 3;
    const int wm   = (warp >> 2) * 32, wn = (warp & 3) * 32;

    const int mat = lane >> 3, r8 = lane & 7;
    const int lb  = lane & 15;
    const unsigned adrA0 = smem_u32(sA) +
        (((wm + (mat & 1) * 8 + r8) * 68 + (mat >> 1) * 4) << 2);
    const unsigned adrA1 = adrA0 + (16 * 68 << 2);
    const unsigned adrB0 = smem_u32(sB) +
        (((wn + (lb & 7)) * 68 + ((lb >> 3) & 1) * 4) << 2);

    float acc[2][4][4] = {};

    for (int k0 = 0; k0 < 768; k0 += 64) {
        #pragma unroll
        for (int e = 0; e < 4; e++) {
            int idx = (e * NTHR + tid) * 4;
            int m = idx >> 6, k = idx & 63;
            float4 v = *(const float4*)&A[(size_t)(row0 + m) * 768 + k0 + k];
            v.x = tf32r(v.x); v.y = tf32r(v.y); v.z = tf32r(v.z); v.w = tf32r(v.w);
            *(float4*)&sA[m * 68 + k] = v;
        }
        {
            int n  = tid & 127;
            int kg = (tid >> 7) * 16;
            #pragma unroll
            for (int g = 0; g < 4; g++) {
                sB[n * 68 + kg + g * 4 + 0] = tf32r(W[(size_t)(k0 + kg + g * 4 + 0) * 768 + col0 + n]);
                sB[n * 68 + kg + g * 4 + 1] = tf32r(W[(size_t)(k0 + kg + g * 4 + 1) * 768 + col0 + n]);
                sB[n * 68 + kg + g * 4 + 2] = tf32r(W[(size_t)(k0 + kg + g * 4 + 2) * 768 + col0 + n]);
                sB[n * 68 + kg + g * 4 + 3] = tf32r(W[(size_t)(k0 + kg + g * 4 + 3) * 768 + col0 + n]);
            }
        }
        __syncthreads();

        #pragma unroll
        for (int ks = 0; ks < 64; ks += 8) {
            const unsigned boff = ks << 2;
            unsigned b0[4], b1[4];
            #pragma unroll
            for (int nt = 0; nt < 4; nt++)
                ldsm_x2(b0[nt], b1[nt], adrB0 + nt * (8 * 68 << 2) + boff);
            #pragma unroll
            for (int mt = 0; mt < 2; mt++) {
                unsigned a0, a1, a2, a3;
                ldsm_x4(a0, a1, a2, a3, (mt ? adrA1 : adrA0) + boff);
                #pragma unroll
                for (int nt = 0; nt < 4; nt++)
                    mma_tf32(acc[mt][nt], a0, a1, a2, a3, b0[nt], b1[nt]);
            }
        }
        __syncthreads();
    }

    #pragma unroll
    for (int mt = 0; mt < 2; mt++) {
        int r = row0 + wm + mt * 16 + gid;
        #pragma unroll
        for (int nt = 0; nt < 4; nt++) {
            int c = col0 + wn + nt * 8 + tig * 2;
            float v00 = acc[mt][nt][0] + bias[c];
            float v01 = acc[mt][nt][1] + bias[c + 1];
            float v10 = acc[mt][nt][2] + bias[c];
            float v11 = acc[mt][nt][3] + bias[c + 1];
            if (out16) {
                *(unsigned*)&out16[(size_t)r * 768 + c]       = bf2(v00, v01);
                *(unsigned*)&out16[(size_t)(r + 8) * 768 + c] = bf2(v10, v11);
            }
            if (outF) {
                float2 w0 = {tf32r(v00), tf32r(v01)};
                float2 w1 = {tf32r(v10), tf32r(v11)};
                *(float2*)&outF[(size_t)r * 768 + c]       = w0;
                *(float2*)&outF[(size_t)(r + 8) * 768 + c] = w1;
            }
        }
    }
}

// ---------------------------------------------------------------------------
// SUM PASS (bf16): job=(bh,i0). Q tile resident (bf16); 16 j-tiles of 64,
// double-buffered raw cp.async bf16 K fills; exp row sums -> g_inv.
// smem (floats): sQ16 @0 (4608) | sK16 @4608 (2x2304) | sMask @9216 (2x64)
//              | sRed @9344 (512)   -> 9856 fl, well under budget
// ---------------------------------------------------------------------------
__device__ void sum_pass(int job, const float* __restrict__ mask, float* smem) {
    __nv_bfloat16* sQ16 = (__nv_bfloat16*)smem;              // 128 x 72
    __nv_bfloat16* sK16 = (__nv_bfloat16*)(smem + 4608);     // 2 x (64 x 72)
    float* sMask = smem + 9216;
    float* sRed  = smem + 9344;

    const int bh = job >> 3;
    const int i0 = (job & 7) * 128;
    const int b  = bh / 12, h = bh % 12;
    const __nv_bfloat16* qb = g_q16 + (size_t)b * S_ * 768 + h * 64;
    const __nv_bfloat16* kb = g_k16 + (size_t)b * S_ * 768 + h * 64;

    const int tid  = threadIdx.x;
    const int warp = tid >> 5, lane = tid & 31;
    const int gid  = lane >> 2, tig = lane & 3;
    const int wm   = (warp >> 2) * 32;
    const int wn16 = (warp & 3) * 16;

    const int mat = lane >> 3, r8 = lane & 7;
    const int lb  = lane & 15;
    const unsigned adrQ0 = smem_u32(sQ16) +
        (wm + (mat & 1) * 8 + r8) * 144 + (mat >> 1) * 16;
    const unsigned adrQ1 = adrQ0 + 16 * 144;
    const unsigned adrKb = smem_u32(sK16) +
        (wn16 + (lb & 7)) * 144 + ((lb >> 3) & 1) * 16;

    const unsigned sQu = smem_u32(sQ16);
    const unsigned sKu = smem_u32(sK16);
    const unsigned sMu = smem_u32(sMask);

    // prologue: Q (bf16, 128 rows x 8 chunks) + K tile 0 + mask 0
    #pragma unroll
    for (int e = 0; e < 2; e++) {
        int idx = e * NTHR + tid;                   // 0..1023
        int m = idx >> 3, c = (idx & 7) * 8;
        cpa16(sQu + (unsigned)(m * 144 + c * 2), &qb[(size_t)(i0 + m) * 768 + c]);
    }
    {
        int j = tid >> 3, c = (tid & 7) * 8;        // 512 chunks
        cpa16(sKu + (unsigned)(j * 144 + c * 2), &kb[(size_t)j * 768 + c]);
    }
    if (tid < 16) cpa16(sMu + tid * 16, &mask[(size_t)b * S_ + tid * 4]);
    cp_commit();

    float rs[2][2] = {};

    for (int jt = 0; jt < 16; jt++) {
        cp_wait0();
        __syncthreads();
        int cur = jt & 1, nxt = cur ^ 1;
        if (jt + 1 < 16) {
            int jb2 = (jt + 1) * 64;
            {
                int j = tid >> 3, c = (tid & 7) * 8;
                cpa16(sKu + (unsigned)(nxt * 9216 + j * 144 + c * 2),
                      &kb[(size_t)(jb2 + j) * 768 + c]);
            }
            if (tid < 16)
                cpa16(sMu + (unsigned)(nxt * 64 + tid * 4) * 4,
                      &mask[(size_t)b * S_ + jb2 + tid * 4]);
            cp_commit();
        }

        const unsigned aK = adrKb + (unsigned)cur * 9216;
        float accS[2][2][4] = {};
        #pragma unroll
        for (int ks = 0; ks < 64; ks += 16) {
            const unsigned boff = ks << 1;
            unsigned b0[2], b1[2];
            #pragma unroll
            for (int nt = 0; nt < 2; nt++)
                ldsm_x2(b0[nt], b1[nt], aK + nt * (8 * 144) + boff);
            #pragma unroll
            for (int mt = 0; mt < 2; mt++) {
                unsigned a0, a1, a2, a3;
                ldsm_x4(a0, a1, a2, a3, (mt ? adrQ1 : adrQ0) + boff);
                #pragma unroll
                for (int nt = 0; nt < 2; nt++)
                    mma_bf16(accS[mt][nt], a0, a1, a2, a3, b0[nt], b1[nt]);
            }
        }

        const float* mk = sMask + cur * 64;
        #pragma unroll
        for (int mt = 0; mt < 2; mt++) {
            #pragma unroll
            for (int nt = 0; nt < 2; nt++) {
                int lc = wn16 + nt * 8 + tig * 2;
                float mk0 = (1.0f - mk[lc])     * -10000.0f;
                float mk1 = (1.0f - mk[lc + 1]) * -10000.0f;
                rs[mt][0] += __expf(accS[mt][nt][0] * 0.125f + mk0)
                           + __expf(accS[mt][nt][1] * 0.125f + mk1);
                rs[mt][1] += __expf(accS[mt][nt][2] * 0.125f + mk0)
                           + __expf(accS[mt][nt][3] * 0.125f + mk1);
            }
        }
    }

    #pragma unroll
    for (int o = 1; o < 4; o <<= 1) {
        rs[0][0] += __shfl_xor_sync(0xFFFFFFFFu, rs[0][0], o);
        rs[0][1] += __shfl_xor_sync(0xFFFFFFFFu, rs[0][1], o);
        rs[1][0] += __shfl_xor_sync(0xFFFFFFFFu, rs[1][0], o);
        rs[1][1] += __shfl_xor_sync(0xFFFFFFFFu, rs[1][1], o);
    }
    __syncthreads();
    if (tig == 0) {
        #pragma unroll
        for (int mt = 0; mt < 2; mt++) {
            sRed[(warp & 3) * 128 + wm + mt * 16 + gid]     = rs[mt][0];
            sRed[(warp & 3) * 128 + wm + mt * 16 + gid + 8] = rs[mt][1];
        }
    }
    __syncthreads();
    if (tid < 128) {
        float s = sRed[tid] + sRed[128 + tid] + sRed[256 + tid] + sRed[384 + tid];
        g_inv[(size_t)bh * S_ + i0 + tid] = 1.0f / s;
    }
    __syncthreads();
}

// ---------------------------------------------------------------------------
// CTX+PROBS PASS: job=(bh,i0). Q resident (tf32); 16 j-tiles of 64,
// double-buffered raw cp.async K (tf32) + V (bf16, ldmatrix.trans).
// Recompute scores -> probs -> attn_out (fp32) + sP (bf16) -> P@V -> g_ctx16.
// smem (floats): sQ @0 (8704) | sK @8704 (2x4352) | sV @17408 (2x2304)
//              | sP @22016 (4608) | sInv @26624 (128) | sMask @26752 (2x64)
// ---------------------------------------------------------------------------
__device__ void ctx_probs_pass(int job, const float* __restrict__ mask,
                               float* __restrict__ attn_out, float* smem) {
    float* sQ = smem;
    float* sK = smem + 8704;
    __nv_bfloat16* sV = (__nv_bfloat16*)(smem + 17408);
    __nv_bfloat16* sP = (__nv_bfloat16*)(smem + 22016);
    float* sInv = smem + 26624;
    float* sMask = smem + 26752;

    const int bh = job >> 3;
    const int i0 = (job & 7) * 128;
    const int b  = bh / 12, h = bh % 12;
    const float* qb = g_q + (size_t)b * S_ * 768 + h * 64;
    const float* kb = g_k + (size_t)b * S_ * 768 + h * 64;
    const __nv_bfloat16* vb = g_v16 + (size_t)b * S_ * 768 + h * 64;

    const int tid  = threadIdx.x;
    const int warp = tid >> 5, lane = tid & 31;
    const int gid  = lane >> 2, tig = lane & 3;
    const int wm   = (warp >> 2) * 32;
    const int wn16 = (warp & 3) * 16;

    const int mat = lane >> 3, r8 = lane & 7;
    const int lb  = lane & 15;
    const unsigned adrQ0 = smem_u32(sQ) +
        (((wm + (mat & 1) * 8 + r8) * 68 + (mat >> 1) * 4) << 2);
    const unsigned adrQ1 = adrQ0 + (16 * 68 << 2);
    const unsigned adrKb = smem_u32(sK) +
        (((wn16 + (lb & 7)) * 68 + ((lb >> 3) & 1) * 4) << 2);
    const unsigned adrPA0 = smem_u32(sP) +
        (wm + (mat & 1) * 8 + r8) * 144 + (mat >> 1) * 16;
    const unsigned adrPA1 = adrPA0 + 16 * 144;
    const unsigned adrVb = smem_u32(sV) + lb * 144 + wn16 * 2;

    const unsigned sQu = smem_u32(sQ);
    const unsigned sKu = smem_u32(sK);
    const unsigned sVu = smem_u32(sV);
    const unsigned sMu = smem_u32(sMask);

    // prologue: Q + K0 + V0 + mask0 (raw byte copies)
    #pragma unroll
    for (int e = 0; e < 4; e++) {
        int idx = e * NTHR + tid;
        int m = idx >> 4, d = (idx & 15) * 4;
        cpa16(sQu + (unsigned)(m * 68 + d) * 4, &qb[(size_t)(i0 + m) * 768 + d]);
    }
    #pragma unroll
    for (int e = 0; e < 2; e++) {
        int idx = e * NTHR + tid;
        int j = idx >> 4, d = (idx & 15) * 4;
        cpa16(sKu + (unsigned)(j * 68 + d) * 4, &kb[(size_t)j * 768 + d]);
    }
    {
        int j = tid >> 3, c = (tid & 7) * 8;
        cpa16(sVu + (unsigned)(j * 144 + c * 2), &vb[(size_t)j * 768 + c]);
    }
    if (tid < 16) cpa16(sMu + tid * 16, &mask[(size_t)b * S_ + tid * 4]);
    cp_commit();
    if (tid < 128) sInv[tid] = g_inv[(size_t)bh * S_ + i0 + tid];

    float accC[2][2][4] = {};

    for (int jt = 0; jt < 16; jt++) {
        cp_wait0();
        __syncthreads();
        int cur = jt & 1, nxt = cur ^ 1;
        int jb = jt * 64;
        if (jt + 1 < 16) {
            int jb2 = jb + 64;
            #pragma unroll
            for (int e = 0; e < 2; e++) {
                int idx = e * NTHR + tid;
                int j = idx >> 4, d = (idx & 15) * 4;
                cpa16(sKu + (unsigned)(nxt * 4352 + j * 68 + d) * 4,
                      &kb[(size_t)(jb2 + j) * 768 + d]);
            }
            {
                int j = tid >> 3, c = (tid & 7) * 8;
                cpa16(sVu + (unsigned)(nxt * 9216 + j * 144 + c * 2),
                      &vb[(size_t)(jb2 + j) * 768 + c]);
            }
            if (tid < 16)
                cpa16(sMu + (unsigned)(nxt * 64 + tid * 4) * 4,
                      &mask[(size_t)b * S_ + jb2 + tid * 4]);
            cp_commit();
        }

        // score mma on current K buffer (m128 x n64, k64) — tf32
        const unsigned aK = adrKb + (unsigned)cur * 4352 * 4;
        float accS[2][2][4] = {};
        #pragma unroll
        for (int ks = 0; ks < 64; ks += 8) {
            const unsigned boff = ks << 2;
            unsigned b0[2], b1[2];
            #pragma unroll
            for (int nt = 0; nt < 2; nt++)
                ldsm_x2(b0[nt], b1[nt], aK + nt * (8 * 68 << 2) + boff);
            #pragma unroll
            for (int mt = 0; mt < 2; mt++) {
                unsigned a0, a1, a2, a3;
                ldsm_x4(a0, a1, a2, a3, (mt ? adrQ1 : adrQ0) + boff);
                #pragma unroll
                for (int nt = 0; nt < 2; nt++)
                    mma_tf32(accS[mt][nt], a0, a1, a2, a3, b0[nt], b1[nt]);
            }
        }

        // exp -> probs -> attn_out (fp32) + sP (bf16)
        const float* mk = sMask + cur * 64;
        #pragma unroll
        for (int mt = 0; mt < 2; mt++) {
            int rl0 = wm + mt * 16 + gid;
            float iv0 = sInv[rl0], iv1 = sInv[rl0 + 8];
            #pragma unroll
            for (int nt = 0; nt < 2; nt++) {
                int lc = wn16 + nt * 8 + tig * 2;
                float mk0 = (1.0f - mk[lc])     * -10000.0f;
                float mk1 = (1.0f - mk[lc + 1]) * -10000.0f;
                float p0 = __expf(accS[mt][nt][0] * 0.125f + mk0) * iv0;
                float p1 = __expf(accS[mt][nt][1] * 0.125f + mk1) * iv0;
                float p2 = __expf(accS[mt][nt][2] * 0.125f + mk0) * iv1;
                float p3 = __expf(accS[mt][nt][3] * 0.125f + mk1) * iv1;
                *(unsigned*)&sP[rl0 * 72 + lc]       = bf2(p0, p1);
                *(unsigned*)&sP[(rl0 + 8) * 72 + lc] = bf2(p2, p3);
                if (attn_out) {
                    size_t ob = (size_t)bh * S_ * S_ + jb + lc;
                    float2 q0 = {p0, p1};
                    float2 q1 = {p2, p3};
                    *(float2*)&attn_out[ob + (size_t)(i0 + rl0) * S_]     = q0;
                    *(float2*)&attn_out[ob + (size_t)(i0 + rl0 + 8) * S_] = q1;
                }
            }
        }
        __syncthreads();   // sP published

        // ctx mma: P (m128 x k64) @ V (k64 x n64), V via ldmatrix.trans
        const unsigned aV = adrVb + (unsigned)cur * 9216;
        #pragma unroll
        for (int ks = 0; ks < 64; ks += 16) {
            unsigned b0[2], b1[2];
            #pragma unroll
            for (int nt = 0; nt < 2; nt++)
                ldsm_x2t(b0[nt], b1[nt], aV + ks * 144 + nt * 16);
            #pragma unroll
            for (int mt = 0; mt < 2; mt++) {
                unsigned a0, a1, a2, a3;
                ldsm_x4(a0, a1, a2, a3, (mt ? adrPA1 : adrPA0) + (ks << 1));
                #pragma unroll
                for (int nt = 0; nt < 2; nt++)
                    mma_bf16(accC[mt][nt], a0, a1, a2, a3, b0[nt], b1[nt]);
            }
        }
    }

    // epilogue: write bf16 context
    #pragma unroll
    for (int mt = 0; mt < 2; mt++) {
        int s = i0 + wm + mt * 16 + gid;
        #pragma unroll
        for (int nt = 0; nt < 2; nt++) {
            int c = h * 64 + wn16 + nt * 8 + tig * 2;
            *(unsigned*)&g_ctx16[(size_t)(b * S_ + s) * 768 + c] =
                bf2(accC[mt][nt][0], accC[mt][nt][1]);
            *(unsigned*)&g_ctx16[(size_t)(b * S_ + s + 8) * 768 + c] =
                bf2(accC[mt][nt][2], accC[mt][nt][3]);
        }
    }
    __syncthreads();
}

// ---------------------------------------------------------------------------
// O PROJECTION: 64x128 tile, BK=64, bf16, raw cp.async double-buffered.
// A = g_ctx16 [m][k]; B = g_wo16 [k][n] via ldmatrix.trans.
// ---------------------------------------------------------------------------
__device__ void oproj_tile(const float* __restrict__ bias, int tileIdx,
                           float* smem) {
    __nv_bfloat16* sA16 = (__nv_bfloat16*)smem;
    __nv_bfloat16* sB16 = (__nv_bfloat16*)(smem + 4608);

    const int row0 = (tileIdx / 6) * 64;
    const int col0 = (tileIdx % 6) * 128;
    const int tid  = threadIdx.x;
    const int warp = tid >> 5, lane = tid & 31;
    const int gid  = lane >> 2, tig = lane & 3;
    const int wm16 = (warp >> 2) * 16;
    const int wn32 = (warp & 3) * 32;

    const int mat = lane >> 3, r8 = lane & 7;
    const int lb  = lane & 15;
    const unsigned adrA = smem_u32(sA16) +
        (wm16 + (mat & 1) * 8 + r8) * 144 + (mat >> 1) * 16;
    const unsigned adrB = smem_u32(sB16) + lb * 272 + wn32 * 2;

    const unsigned sAu = smem_u32(sA16);
    const unsigned sBu = smem_u32(sB16);

    // prologue: k0 = 0
    {
        int m = tid >> 3, c = (tid & 7) * 8;
        cpa16(sAu + (unsigned)(m * 144 + c * 2),
              &g_ctx16[(size_t)(row0 + m) * 768 + c]);
        #pragma unroll
        for (int e = 0; e < 2; e++) {
            int idx = e * NTHR + tid;
            int k = idx >> 4, n = (idx & 15) * 8;
            cpa16(sBu + (unsigned)(k * 272 + n * 2),
                  &g_wo16[(size_t)k * 768 + col0 + n]);
        }
    }
    cp_commit();

    float acc[4][4] = {};

    for (int s = 0; s < 12; s++) {
        cp_wait0();
        __syncthreads();
        int cur = s & 1, nxt = cur ^ 1;
        if (s + 1 < 12) {
            int k0 = (s + 1) * 64;
            int m = tid >> 3, c = (tid & 7) * 8;
            cpa16(sAu + (unsigned)(nxt * 9216 + m * 144 + c * 2),
                  &g_ctx16[(size_t)(row0 + m) * 768 + k0 + c]);
            #pragma unroll
            for (int e = 0; e < 2; e++) {
                int idx = e * NTHR + tid;
                int k = idx >> 4, n = (idx & 15) * 8;
                cpa16(sBu + (unsigned)(nxt * 17408 + k * 272 + n * 2),
                      &g_wo16[(size_t)(k0 + k) * 768 + col0 + n]);
            }
            cp_commit();
        }

        const unsigned aA = adrA + (unsigned)cur * 9216;
        const unsigned aB = adrB + (unsigned)cur * 17408;
        #pragma unroll
        for (int ks = 0; ks < 64; ks += 16) {
            unsigned b0[4], b1[4];
            #pragma unroll
            for (int nt = 0; nt < 4; nt++)
                ldsm_x2t(b0[nt], b1[nt], aB + ks * 272 + nt * 16);
            unsigned a0, a1, a2, a3;
            ldsm_x4(a0, a1, a2, a3, aA + (ks << 1));
            #pragma unroll
            for (int nt = 0; nt < 4; nt++)
                mma_bf16(acc[nt], a0, a1, a2, a3, b0[nt], b1[nt]);
        }
    }

    {
        int r = row0 + wm16 + gid;
        #pragma unroll
        for (int nt = 0; nt < 4; nt++) {
            int c = col0 + wn32 + nt * 8 + tig * 2;
            float2 v0 = {acc[nt][0] + bias[c], acc[nt][1] + bias[c + 1]};
            float2 v1 = {acc[nt][2] + bias[c], acc[nt][3] + bias[c + 1]};
            *(float2*)&g_proj[(size_t)r * 768 + c]       = v0;
            *(float2*)&g_proj[(size_t)(r + 8) * 768 + c] = v1;
        }
    }
    __syncthreads();
}

// ---------------------------------------------------------------------------
// The single fused kernel.
// ---------------------------------------------------------------------------
__global__ __launch_bounds__(NTHR, 2)
void fused_kernel(const float* __restrict__ query, const float* __restrict__ key,
                  const float* __restrict__ value, const float* __restrict__ mask,
                  const float* __restrict__ Wq, const float* __restrict__ bq,
                  const float* __restrict__ Wk, const float* __restrict__ bk,
                  const float* __restrict__ Wv, const float* __restrict__ bv,
                  const float* __restrict__ Wo, const float* __restrict__ bo,
                  const float* __restrict__ gamma, const float* __restrict__ beta,
                  float* __restrict__ out, float* __restrict__ attn_out) {
    extern __shared__ float smem[];
    const int tid  = threadIdx.x;
    const int warp = tid >> 5, lane = tid & 31;

    // ---- Phase 0: convert Wo -> bf16 (consumed in phase 4, after barriers) --
    for (int i = blockIdx.x * NTHR + tid; i < 147456; i += NBLK * NTHR) {
        float4 w = ((const float4*)Wo)[i];
        uint2 u = {bf2(w.x, w.y), bf2(w.z, w.w)};
        ((uint2*)g_wo16)[i] = u;
    }

    // ---- Phase 1: QKV projections (1152 jobs) ----
    for (int job = blockIdx.x; job < 3 * 384; job += NBLK) {
        int which = job / 384;
        int t = job % 384;
        const float* A  = (which == 0) ? query : (which == 1) ? key : value;
        const float* W  = (which == 0) ? Wq    : (which == 1) ? Wk  : Wv;
        const float* bb = (which == 0) ? bq    : (which == 1) ? bk  : bv;
        float* OF = (which == 0) ? g_q : (which == 1) ? g_k : 0;
        __nv_bfloat16* O16 = (which == 0) ? g_q16
                            : (which == 1) ? g_k16 : g_v16;
        qkv_tile(A, W, bb, OF, O16, t, smem, smem + 8704);
    }
    grid_barrier();

    // ---- Phase 2: sum pass (768 jobs, bf16) ----
    for (int job = blockIdx.x; job < 768; job += NBLK)
        sum_pass(job, mask, smem);
    grid_barrier();

    // ---- Phase 3: ctx + probs pass (768 jobs) ----
    for (int job = blockIdx.x; job < 768; job += NBLK)
        ctx_probs_pass(job, mask, attn_out, smem);
    grid_barrier();

    // ---- Phase 4: output projection (768 jobs) ----
    for (int t = blockIdx.x; t < 768; t += NBLK)
        oproj_tile(bo, t, smem);
    grid_barrier();

    // ---- Phase 5: residual + LayerNorm — warp per row ----
    for (int row = blockIdx.x * 16 + warp; row < MROWS; row += NBLK * 16) {
        const float* pp = g_proj + (size_t)row * 768;
        const float* op = query + (size_t)row * 768;

        float4 x[6];
        float sum = 0.0f;
        #pragma unroll
        for (int v = 0; v < 6; v++) {
            int off = v * 128 + lane * 4;
            float4 a = *(const float4*)&pp[off];
            float4 o = *(const float4*)&op[off];
            x[v].x = a.x + o.x; x[v].y = a.y + o.y;
            x[v].z = a.z + o.z; x[v].w = a.w + o.w;
            sum += x[v].x + x[v].y + x[v].z + x[v].w;
        }
        #pragma unroll
        for (int o = 16; o > 0; o >>= 1)
            sum += __shfl_xor_sync(0xFFFFFFFFu, sum, o);
        const float mu = sum * (1.0f / 768.0f);

        float var = 0.0f;
        #pragma unroll
        for (int v = 0; v < 6; v++) {
            float dx = x[v].x - mu, dy = x[v].y - mu;
            float dz = x[v].z - mu, dw = x[v].w - mu;
            var += dx * dx + dy * dy + dz * dz + dw * dw;
        }
        #pragma unroll
        for (int o = 16; o > 0; o >>= 1)
            var += __shfl_xor_sync(0xFFFFFFFFu, var, o);
        const float inv = rsqrtf(var * (1.0f / 768.0f) + 1e-8f);

        #pragma unroll
        for (int v = 0; v < 6; v++) {
            int off = v * 128 + lane * 4;
            float4 g = *(const float4*)&gamma[off];
            float4 bt = *(const float4*)&beta[off];
            float4 r;
            r.x = (x[v].x - mu) * inv * g.x + bt.x;
            r.y = (x[v].y - mu) * inv * g.y + bt.y;
            r.z = (x[v].z - mu) * inv * g.z + bt.z;
            r.w = (x[v].w - mu) * inv * g.w + bt.w;
            *(float4*)&out[(size_t)row * 768 + off] = r;
        }
    }
}

// ---------------------------------------------------------------------------
// Launch
// ---------------------------------------------------------------------------
extern "C" void kernel_launch(void* const* d_in, const int* in_sizes, int n_in,
                              void* d_out, int out_size) {
    const float* big[3]  = {0, 0, 0};
    const float* mats[4] = {0, 0, 0, 0};
    const float* vecs[6] = {0, 0, 0, 0, 0, 0};
    const float* mask = 0;
    int nb = 0, nm = 0, nv = 0;
    for (int i = 0; i < n_in; i++) {
        const float* p = (const float*)d_in[i];
        switch (in_sizes[i]) {
            case 6291456: if (nb < 3) big[nb++] = p;  break;
            case 589824:  if (nm < 4) mats[nm++] = p; break;
            case 768:     if (nv < 6) vecs[nv++] = p; break;
            case 8192:    mask = p;                   break;
            default: break;
        }
    }
    float* out = (float*)d_out;
    float* attn_out = ((long long)out_size >= (long long)BSD + BHSS)
                          ? (out + BSD) : 0;

    cudaFuncSetAttribute(fused_kernel,
                         cudaFuncAttributeMaxDynamicSharedMemorySize, DYN_SMEM);

    fused_kernel<<<NBLK, NTHR, DYN_SMEM>>>(big[0], big[1], big[2], mask,
                                           mats[0], vecs[0], mats[1], vecs[1],
                                           mats[2], vecs[2], mats[3], vecs[3],
                                           vecs[4], vecs[5], out, attn_out);
}

// round 17
// speedup vs baseline: 1.5653x; 1.3191x over previous
#include <cuda_runtime.h>
#include <cuda_fp16.h>

// Problem constants
#define B_    8
#define S_    1024
#define MROWS 8192                    // B*S
#define BSD   6291456                 // MROWS*D
#define BHSS  100663296LL             // B*H*S*S
#define WSZ   589824                  // 768*768

#define NBLK  296                     // 2 per SM x 148 SMs, co-resident
#define NTHR  512
#define DYN_SMEM 74752                // ctx pass high-water: 18688 floats

// Device-global scratch — used ONLY within a single kernel launch.
__device__ __half g_in16[3 * BSD];         // query/key/value, fp16
__device__ __half g_w16[4 * WSZ];          // Wq,Wk,Wv,Wo, fp16
__device__ __half g_q16[BSD];
__device__ __half g_k16[BSD];
__device__ __half g_v16[BSD];
__device__ __half g_ctx16[BSD];
__device__ float g_proj[BSD];
__device__ float g_inv[98304];             // per-row 1/sum

// Software grid barrier (generation counter; replay-safe).
__device__ unsigned g_bar_count;
__device__ unsigned g_bar_gen;

__device__ __forceinline__ void grid_barrier() {
    __syncthreads();
    if (threadIdx.x == 0) {
        __threadfence();
        unsigned gen = g_bar_gen;
        unsigned old = atomicAdd(&g_bar_count, 1u);
        if (old == (unsigned)(gridDim.x - 1)) {
            g_bar_count = 0;
            __threadfence();
            atomicAdd(&g_bar_gen, 1u);
        } else {
            while (atomicAdd(&g_bar_gen, 0u) == gen) { __nanosleep(64); }
        }
        __threadfence();
    }
    __syncthreads();
}

__device__ __forceinline__ unsigned hf2(float a, float b) {
    __half2 h = __floats2half2_rn(a, b);
    return *(unsigned*)&h;
}

__device__ __forceinline__ void cpa16(unsigned dst, const void* src) {
    asm volatile("cp.async.cg.shared.global [%0], [%1], 16;"
                 :: "r"(dst), "l"(src));
}
__device__ __forceinline__ void cp_commit() {
    asm volatile("cp.async.commit_group;" ::: "memory");
}
__device__ __forceinline__ void cp_wait0() {
    asm volatile("cp.async.wait_group 0;" ::: "memory");
}

__device__ __forceinline__ void mma_fp16(float* acc, unsigned a0, unsigned a1,
                                         unsigned a2, unsigned a3,
                                         unsigned b0, unsigned b1) {
    asm volatile(
        "mma.sync.aligned.m16n8k16.row.col.f32.f16.f16.f32 "
        "{%0,%1,%2,%3}, {%4,%5,%6,%7}, {%8,%9}, {%0,%1,%2,%3};"
        : "+f"(acc[0]), "+f"(acc[1]), "+f"(acc[2]), "+f"(acc[3])
        : "r"(a0), "r"(a1), "r"(a2), "r"(a3), "r"(b0), "r"(b1));
}
__device__ __forceinline__ void ldsm_x4(unsigned& r0, unsigned& r1,
                                        unsigned& r2, unsigned& r3,
                                        unsigned addr) {
    asm volatile("ldmatrix.sync.aligned.m8n8.x4.shared.b16 {%0,%1,%2,%3}, [%4];"
                 : "=r"(r0), "=r"(r1), "=r"(r2), "=r"(r3) : "r"(addr));
}
__device__ __forceinline__ void ldsm_x2(unsigned& r0, unsigned& r1,
                                        unsigned addr) {
    asm volatile("ldmatrix.sync.aligned.m8n8.x2.shared.b16 {%0,%1}, [%2];"
                 : "=r"(r0), "=r"(r1) : "r"(addr));
}
__device__ __forceinline__ void ldsm_x2t(unsigned& r0, unsigned& r1,
                                         unsigned addr) {
    asm volatile("ldmatrix.sync.aligned.m8n8.x2.trans.shared.b16 {%0,%1}, [%2];"
                 : "=r"(r0), "=r"(r1) : "r"(addr));
}
__device__ __forceinline__ unsigned smem_u32(const void* p) {
    return (unsigned)__cvta_generic_to_shared(p);
}

// ---------------------------------------------------------------------------
// Phase 1: fp16 GEMM, 128x128 tile, BK=64, raw cp.async double-buffered.
// A = in16 [m][k]; B = w16 [k][n] via ldmatrix.trans; out fp16 + fp32 bias.
// smem (floats): sA @0 (2 x 4608) | sB @9216 (2 x 4352) -> 17920 fl
// ---------------------------------------------------------------------------
__device__ void qkv16_tile(const __half* __restrict__ A16,
                           const __half* __restrict__ W16,
                           const float* __restrict__ bias,
                           __half* __restrict__ out16,
                           int tileIdx, float* smem) {
    __half* sA = (__half*)smem;                 // 2 x (128 x 72)
    __half* sB = (__half*)(smem + 9216);        // 2 x (64 x 136)

    const int row0 = (tileIdx / 6) * 128;
    const int col0 = (tileIdx % 6) * 128;
    const int tid  = threadIdx.x;
    const int warp = tid >> 5, lane = tid & 31;
    const int gid  = lane >> 2, tig = lane & 3;
    const int wm   = (warp >> 2) * 32, wn = (warp & 3) * 32;

    const int mat = lane >> 3, r8 = lane & 7;
    const int lb  = lane & 15;
    const unsigned adrA = smem_u32(sA) +
        (wm + (mat & 1) * 8 + r8) * 144 + (mat >> 1) * 16;
    const unsigned adrB = smem_u32(sB) + lb * 272 + wn * 2;

    const unsigned sAu = smem_u32(sA);
    const unsigned sBu = smem_u32(sB);

    // prologue: k0 = 0
    #pragma unroll
    for (int e = 0; e < 2; e++) {
        int idx = e * NTHR + tid;
        int m = idx >> 3, c = (idx & 7) * 8;
        cpa16(sAu + (unsigned)(m * 144 + c * 2),
              &A16[(size_t)(row0 + m) * 768 + c]);
        int k = idx >> 4, n = (idx & 15) * 8;
        cpa16(sBu + (unsigned)(k * 272 + n * 2),
              &W16[(size_t)k * 768 + col0 + n]);
    }
    cp_commit();

    float acc[2][4][4] = {};

    for (int s = 0; s < 12; s++) {
        cp_wait0();
        __syncthreads();
        int cur = s & 1, nxt = cur ^ 1;
        if (s + 1 < 12) {
            int k0 = (s + 1) * 64;
            #pragma unroll
            for (int e = 0; e < 2; e++) {
                int idx = e * NTHR + tid;
                int m = idx >> 3, c = (idx & 7) * 8;
                cpa16(sAu + (unsigned)(nxt * 18432 + m * 144 + c * 2),
                      &A16[(size_t)(row0 + m) * 768 + k0 + c]);
                int k = idx >> 4, n = (idx & 15) * 8;
                cpa16(sBu + (unsigned)(nxt * 17408 + k * 272 + n * 2),
                      &W16[(size_t)(k0 + k) * 768 + col0 + n]);
            }
            cp_commit();
        }

        const unsigned aA = adrA + (unsigned)cur * 18432;
        const unsigned aB = adrB + (unsigned)cur * 17408;
        #pragma unroll
        for (int ks = 0; ks < 64; ks += 16) {
            unsigned b0[4], b1[4];
            #pragma unroll
            for (int nt = 0; nt < 4; nt++)
                ldsm_x2t(b0[nt], b1[nt], aB + ks * 272 + nt * 16);
            #pragma unroll
            for (int mt = 0; mt < 2; mt++) {
                unsigned a0, a1, a2, a3;
                ldsm_x4(a0, a1, a2, a3, aA + mt * (16 * 144) + (ks << 1));
                #pragma unroll
                for (int nt = 0; nt < 4; nt++)
                    mma_fp16(acc[mt][nt], a0, a1, a2, a3, b0[nt], b1[nt]);
            }
        }
        __syncthreads();
    }

    #pragma unroll
    for (int mt = 0; mt < 2; mt++) {
        int r = row0 + wm + mt * 16 + gid;
        #pragma unroll
        for (int nt = 0; nt < 4; nt++) {
            int c = col0 + wn + nt * 8 + tig * 2;
            *(unsigned*)&out16[(size_t)r * 768 + c] =
                hf2(acc[mt][nt][0] + bias[c], acc[mt][nt][1] + bias[c + 1]);
            *(unsigned*)&out16[(size_t)(r + 8) * 768 + c] =
                hf2(acc[mt][nt][2] + bias[c], acc[mt][nt][3] + bias[c + 1]);
        }
    }
}

// ---------------------------------------------------------------------------
// SUM PASS (fp16): job=(bh,i0). Q tile resident; 16 j-tiles of 64,
// double-buffered raw cp.async fp16 K fills; exp row sums -> g_inv.
// smem (floats): sQ16 @0 (4608) | sK16 @4608 (2x2304) | sMask @9216 (2x64)
//              | sRed @9344 (512)
// ---------------------------------------------------------------------------
__device__ void sum_pass(int job, const float* __restrict__ mask, float* smem) {
    __half* sQ16 = (__half*)smem;              // 128 x 72
    __half* sK16 = (__half*)(smem + 4608);     // 2 x (64 x 72)
    float* sMask = smem + 9216;
    float* sRed  = smem + 9344;

    const int bh = job >> 3;
    const int i0 = (job & 7) * 128;
    const int b  = bh / 12, h = bh % 12;
    const __half* qb = g_q16 + (size_t)b * S_ * 768 + h * 64;
    const __half* kb = g_k16 + (size_t)b * S_ * 768 + h * 64;

    const int tid  = threadIdx.x;
    const int warp = tid >> 5, lane = tid & 31;
    const int gid  = lane >> 2, tig = lane & 3;
    const int wm   = (warp >> 2) * 32;
    const int wn16 = (warp & 3) * 16;

    const int mat = lane >> 3, r8 = lane & 7;
    const int lb  = lane & 15;
    const unsigned adrQ0 = smem_u32(sQ16) +
        (wm + (mat & 1) * 8 + r8) * 144 + (mat >> 1) * 16;
    const unsigned adrQ1 = adrQ0 + 16 * 144;
    const unsigned adrKb = smem_u32(sK16) +
        (wn16 + (lb & 7)) * 144 + ((lb >> 3) & 1) * 16;

    const unsigned sQu = smem_u32(sQ16);
    const unsigned sKu = smem_u32(sK16);
    const unsigned sMu = smem_u32(sMask);

    #pragma unroll
    for (int e = 0; e < 2; e++) {
        int idx = e * NTHR + tid;
        int m = idx >> 3, c = (idx & 7) * 8;
        cpa16(sQu + (unsigned)(m * 144 + c * 2), &qb[(size_t)(i0 + m) * 768 + c]);
    }
    {
        int j = tid >> 3, c = (tid & 7) * 8;
        cpa16(sKu + (unsigned)(j * 144 + c * 2), &kb[(size_t)j * 768 + c]);
    }
    if (tid < 16) cpa16(sMu + tid * 16, &mask[(size_t)b * S_ + tid * 4]);
    cp_commit();

    float rs[2][2] = {};

    for (int jt = 0; jt < 16; jt++) {
        cp_wait0();
        __syncthreads();
        int cur = jt & 1, nxt = cur ^ 1;
        if (jt + 1 < 16) {
            int jb2 = (jt + 1) * 64;
            {
                int j = tid >> 3, c = (tid & 7) * 8;
                cpa16(sKu + (unsigned)(nxt * 9216 + j * 144 + c * 2),
                      &kb[(size_t)(jb2 + j) * 768 + c]);
            }
            if (tid < 16)
                cpa16(sMu + (unsigned)(nxt * 64 + tid * 4) * 4,
                      &mask[(size_t)b * S_ + jb2 + tid * 4]);
            cp_commit();
        }

        const unsigned aK = adrKb + (unsigned)cur * 9216;
        float accS[2][2][4] = {};
        #pragma unroll
        for (int ks = 0; ks < 64; ks += 16) {
            const unsigned boff = ks << 1;
            unsigned b0[2], b1[2];
            #pragma unroll
            for (int nt = 0; nt < 2; nt++)
                ldsm_x2(b0[nt], b1[nt], aK + nt * (8 * 144) + boff);
            #pragma unroll
            for (int mt = 0; mt < 2; mt++) {
                unsigned a0, a1, a2, a3;
                ldsm_x4(a0, a1, a2, a3, (mt ? adrQ1 : adrQ0) + boff);
                #pragma unroll
                for (int nt = 0; nt < 2; nt++)
                    mma_fp16(accS[mt][nt], a0, a1, a2, a3, b0[nt], b1[nt]);
            }
        }

        const float* mk = sMask + cur * 64;
        #pragma unroll
        for (int mt = 0; mt < 2; mt++) {
            #pragma unroll
            for (int nt = 0; nt < 2; nt++) {
                int lc = wn16 + nt * 8 + tig * 2;
                float mk0 = (1.0f - mk[lc])     * -10000.0f;
                float mk1 = (1.0f - mk[lc + 1]) * -10000.0f;
                rs[mt][0] += __expf(accS[mt][nt][0] * 0.125f + mk0)
                           + __expf(accS[mt][nt][1] * 0.125f + mk1);
                rs[mt][1] += __expf(accS[mt][nt][2] * 0.125f + mk0)
                           + __expf(accS[mt][nt][3] * 0.125f + mk1);
            }
        }
    }

    #pragma unroll
    for (int o = 1; o < 4; o <<= 1) {
        rs[0][0] += __shfl_xor_sync(0xFFFFFFFFu, rs[0][0], o);
        rs[0][1] += __shfl_xor_sync(0xFFFFFFFFu, rs[0][1], o);
        rs[1][0] += __shfl_xor_sync(0xFFFFFFFFu, rs[1][0], o);
        rs[1][1] += __shfl_xor_sync(0xFFFFFFFFu, rs[1][1], o);
    }
    __syncthreads();
    if (tig == 0) {
        #pragma unroll
        for (int mt = 0; mt < 2; mt++) {
            sRed[(warp & 3) * 128 + wm + mt * 16 + gid]     = rs[mt][0];
            sRed[(warp & 3) * 128 + wm + mt * 16 + gid + 8] = rs[mt][1];
        }
    }
    __syncthreads();
    if (tid < 128) {
        float s = sRed[tid] + sRed[128 + tid] + sRed[256 + tid] + sRed[384 + tid];
        g_inv[(size_t)bh * S_ + i0 + tid] = 1.0f / s;
    }
    __syncthreads();
}

// ---------------------------------------------------------------------------
// CTX+PROBS PASS (fp16): job=(bh,i0). Q resident; 16 j-tiles of 64,
// double-buffered raw cp.async K + V. Recompute scores (fp16 mma) -> probs
// (fp32) -> attn_out + sP (fp16) -> P@V (fp16 mma) -> g_ctx16.
// smem (floats): sQ @0 (4608) | sK @4608 (2x2304) | sV @9216 (2x2304)
//              | sP @13824 (4608) | sInv @18432 (128) | sMask @18560 (2x64)
// total = 18688 floats = 74752 B
// ---------------------------------------------------------------------------
__device__ void ctx_probs_pass(int job, const float* __restrict__ mask,
                               float* __restrict__ attn_out, float* smem) {
    __half* sQ = (__half*)smem;                 // 128 x 72
    __half* sK = (__half*)(smem + 4608);        // 2 x (64 x 72)
    __half* sV = (__half*)(smem + 9216);        // 2 x (64 x 72)
    __half* sP = (__half*)(smem + 13824);       // 128 x 72
    float* sInv = smem + 18432;
    float* sMask = smem + 18560;

    const int bh = job >> 3;
    const int i0 = (job & 7) * 128;
    const int b  = bh / 12, h = bh % 12;
    const __half* qb = g_q16 + (size_t)b * S_ * 768 + h * 64;
    const __half* kb = g_k16 + (size_t)b * S_ * 768 + h * 64;
    const __half* vb = g_v16 + (size_t)b * S_ * 768 + h * 64;

    const int tid  = threadIdx.x;
    const int warp = tid >> 5, lane = tid & 31;
    const int gid  = lane >> 2, tig = lane & 3;
    const int wm   = (warp >> 2) * 32;
    const int wn16 = (warp & 3) * 16;

    const int mat = lane >> 3, r8 = lane & 7;
    const int lb  = lane & 15;
    const unsigned adrQ0 = smem_u32(sQ) +
        (wm + (mat & 1) * 8 + r8) * 144 + (mat >> 1) * 16;
    const unsigned adrQ1 = adrQ0 + 16 * 144;
    const unsigned adrKb = smem_u32(sK) +
        (wn16 + (lb & 7)) * 144 + ((lb >> 3) & 1) * 16;
    const unsigned adrPA0 = smem_u32(sP) +
        (wm + (mat & 1) * 8 + r8) * 144 + (mat >> 1) * 16;
    const unsigned adrPA1 = adrPA0 + 16 * 144;
    const unsigned adrVb = smem_u32(sV) + lb * 144 + wn16 * 2;

    const unsigned sQu = smem_u32(sQ);
    const unsigned sKu = smem_u32(sK);
    const unsigned sVu = smem_u32(sV);
    const unsigned sMu = smem_u32(sMask);

    // prologue: Q + K0 + V0 + mask0 (raw byte copies)
    #pragma unroll
    for (int e = 0; e < 2; e++) {
        int idx = e * NTHR + tid;
        int m = idx >> 3, c = (idx & 7) * 8;
        cpa16(sQu + (unsigned)(m * 144 + c * 2), &qb[(size_t)(i0 + m) * 768 + c]);
    }
    {
        int j = tid >> 3, c = (tid & 7) * 8;
        cpa16(sKu + (unsigned)(j * 144 + c * 2), &kb[(size_t)j * 768 + c]);
        cpa16(sVu + (unsigned)(j * 144 + c * 2), &vb[(size_t)j * 768 + c]);
    }
    if (tid < 16) cpa16(sMu + tid * 16, &mask[(size_t)b * S_ + tid * 4]);
    cp_commit();
    if (tid < 128) sInv[tid] = g_inv[(size_t)bh * S_ + i0 + tid];

    float accC[2][2][4] = {};

    for (int jt = 0; jt < 16; jt++) {
        cp_wait0();
        __syncthreads();
        int cur = jt & 1, nxt = cur ^ 1;
        int jb = jt * 64;
        if (jt + 1 < 16) {
            int jb2 = jb + 64;
            {
                int j = tid >> 3, c = (tid & 7) * 8;
                cpa16(sKu + (unsigned)(nxt * 9216 + j * 144 + c * 2),
                      &kb[(size_t)(jb2 + j) * 768 + c]);
                cpa16(sVu + (unsigned)(nxt * 9216 + j * 144 + c * 2),
                      &vb[(size_t)(jb2 + j) * 768 + c]);
            }
            if (tid < 16)
                cpa16(sMu + (unsigned)(nxt * 64 + tid * 4) * 4,
                      &mask[(size_t)b * S_ + jb2 + tid * 4]);
            cp_commit();
        }

        // score mma (fp16, m128 x n64, k64)
        const unsigned aK = adrKb + (unsigned)cur * 9216;
        float accS[2][2][4] = {};
        #pragma unroll
        for (int ks = 0; ks < 64; ks += 16) {
            const unsigned boff = ks << 1;
            unsigned b0[2], b1[2];
            #pragma unroll
            for (int nt = 0; nt < 2; nt++)
                ldsm_x2(b0[nt], b1[nt], aK + nt * (8 * 144) + boff);
            #pragma unroll
            for (int mt = 0; mt < 2; mt++) {
                unsigned a0, a1, a2, a3;
                ldsm_x4(a0, a1, a2, a3, (mt ? adrQ1 : adrQ0) + boff);
                #pragma unroll
                for (int nt = 0; nt < 2; nt++)
                    mma_fp16(accS[mt][nt], a0, a1, a2, a3, b0[nt], b1[nt]);
            }
        }

        // exp -> probs -> attn_out (fp32) + sP (fp16)
        const float* mk = sMask + cur * 64;
        #pragma unroll
        for (int mt = 0; mt < 2; mt++) {
            int rl0 = wm + mt * 16 + gid;
            float iv0 = sInv[rl0], iv1 = sInv[rl0 + 8];
            #pragma unroll
            for (int nt = 0; nt < 2; nt++) {
                int lc = wn16 + nt * 8 + tig * 2;
                float mk0 = (1.0f - mk[lc])     * -10000.0f;
                float mk1 = (1.0f - mk[lc + 1]) * -10000.0f;
                float p0 = __expf(accS[mt][nt][0] * 0.125f + mk0) * iv0;
                float p1 = __expf(accS[mt][nt][1] * 0.125f + mk1) * iv0;
                float p2 = __expf(accS[mt][nt][2] * 0.125f + mk0) * iv1;
                float p3 = __expf(accS[mt][nt][3] * 0.125f + mk1) * iv1;
                *(unsigned*)&sP[rl0 * 72 + lc]       = hf2(p0, p1);
                *(unsigned*)&sP[(rl0 + 8) * 72 + lc] = hf2(p2, p3);
                if (attn_out) {
                    size_t ob = (size_t)bh * S_ * S_ + jb + lc;
                    float2 q0 = {p0, p1};
                    float2 q1 = {p2, p3};
                    *(float2*)&attn_out[ob + (size_t)(i0 + rl0) * S_]     = q0;
                    *(float2*)&attn_out[ob + (size_t)(i0 + rl0 + 8) * S_] = q1;
                }
            }
        }
        __syncthreads();   // sP published

        // ctx mma: P (m128 x k64) @ V (k64 x n64), V via ldmatrix.trans
        const unsigned aV = adrVb + (unsigned)cur * 9216;
        #pragma unroll
        for (int ks = 0; ks < 64; ks += 16) {
            unsigned b0[2], b1[2];
            #pragma unroll
            for (int nt = 0; nt < 2; nt++)
                ldsm_x2t(b0[nt], b1[nt], aV + ks * 144 + nt * 16);
            #pragma unroll
            for (int mt = 0; mt < 2; mt++) {
                unsigned a0, a1, a2, a3;
                ldsm_x4(a0, a1, a2, a3, (mt ? adrPA1 : adrPA0) + (ks << 1));
                #pragma unroll
                for (int nt = 0; nt < 2; nt++)
                    mma_fp16(accC[mt][nt], a0, a1, a2, a3, b0[nt], b1[nt]);
            }
        }
    }

    // epilogue: write fp16 context
    #pragma unroll
    for (int mt = 0; mt < 2; mt++) {
        int s = i0 + wm + mt * 16 + gid;
        #pragma unroll
        for (int nt = 0; nt < 2; nt++) {
            int c = h * 64 + wn16 + nt * 8 + tig * 2;
            *(unsigned*)&g_ctx16[(size_t)(b * S_ + s) * 768 + c] =
                hf2(accC[mt][nt][0], accC[mt][nt][1]);
            *(unsigned*)&g_ctx16[(size_t)(b * S_ + s + 8) * 768 + c] =
                hf2(accC[mt][nt][2], accC[mt][nt][3]);
        }
    }
    __syncthreads();
}

// ---------------------------------------------------------------------------
// O PROJECTION: 64x128 tile, BK=64, fp16, raw cp.async double-buffered.
// A = g_ctx16 [m][k]; B = Wo fp16 [k][n] via ldmatrix.trans.
// smem (floats): sA16 @0 (2 x 2304) | sB16 @4608 (2 x 4352)
// ---------------------------------------------------------------------------
__device__ void oproj_tile(const float* __restrict__ bias, int tileIdx,
                           float* smem) {
    __half* sA16 = (__half*)smem;
    __half* sB16 = (__half*)(smem + 4608);
    const __half* wo = g_w16 + 3 * (size_t)WSZ;

    const int row0 = (tileIdx / 6) * 64;
    const int col0 = (tileIdx % 6) * 128;
    const int tid  = threadIdx.x;
    const int warp = tid >> 5, lane = tid & 31;
    const int gid  = lane >> 2, tig = lane & 3;
    const int wm16 = (warp >> 2) * 16;
    const int wn32 = (warp & 3) * 32;

    const int mat = lane >> 3, r8 = lane & 7;
    const int lb  = lane & 15;
    const unsigned adrA = smem_u32(sA16) +
        (wm16 + (mat & 1) * 8 + r8) * 144 + (mat >> 1) * 16;
    const unsigned adrB = smem_u32(sB16) + lb * 272 + wn32 * 2;

    const unsigned sAu = smem_u32(sA16);
    const unsigned sBu = smem_u32(sB16);

    // prologue: k0 = 0
    {
        int m = tid >> 3, c = (tid & 7) * 8;
        cpa16(sAu + (unsigned)(m * 144 + c * 2),
              &g_ctx16[(size_t)(row0 + m) * 768 + c]);
        #pragma unroll
        for (int e = 0; e < 2; e++) {
            int idx = e * NTHR + tid;
            int k = idx >> 4, n = (idx & 15) * 8;
            cpa16(sBu + (unsigned)(k * 272 + n * 2),
                  &wo[(size_t)k * 768 + col0 + n]);
        }
    }
    cp_commit();

    float acc[4][4] = {};

    for (int s = 0; s < 12; s++) {
        cp_wait0();
        __syncthreads();
        int cur = s & 1, nxt = cur ^ 1;
        if (s + 1 < 12) {
            int k0 = (s + 1) * 64;
            int m = tid >> 3, c = (tid & 7) * 8;
            cpa16(sAu + (unsigned)(nxt * 9216 + m * 144 + c * 2),
                  &g_ctx16[(size_t)(row0 + m) * 768 + k0 + c]);
            #pragma unroll
            for (int e = 0; e < 2; e++) {
                int idx = e * NTHR + tid;
                int k = idx >> 4, n = (idx & 15) * 8;
                cpa16(sBu + (unsigned)(nxt * 17408 + k * 272 + n * 2),
                      &wo[(size_t)(k0 + k) * 768 + col0 + n]);
            }
            cp_commit();
        }

        const unsigned aA = adrA + (unsigned)cur * 9216;
        const unsigned aB = adrB + (unsigned)cur * 17408;
        #pragma unroll
        for (int ks = 0; ks < 64; ks += 16) {
            unsigned b0[4], b1[4];
            #pragma unroll
            for (int nt = 0; nt < 4; nt++)
                ldsm_x2t(b0[nt], b1[nt], aB + ks * 272 + nt * 16);
            unsigned a0, a1, a2, a3;
            ldsm_x4(a0, a1, a2, a3, aA + (ks << 1));
            #pragma unroll
            for (int nt = 0; nt < 4; nt++)
                mma_fp16(acc[nt], a0, a1, a2, a3, b0[nt], b1[nt]);
        }
    }

    {
        int r = row0 + wm16 + gid;
        #pragma unroll
        for (int nt = 0; nt < 4; nt++) {
            int c = col0 + wn32 + nt * 8 + tig * 2;
            float2 v0 = {acc[nt][0] + bias[c], acc[nt][1] + bias[c + 1]};
            float2 v1 = {acc[nt][2] + bias[c], acc[nt][3] + bias[c + 1]};
            *(float2*)&g_proj[(size_t)r * 768 + c]       = v0;
            *(float2*)&g_proj[(size_t)(r + 8) * 768 + c] = v1;
        }
    }
    __syncthreads();
}

// ---------------------------------------------------------------------------
// The single fused kernel.
// ---------------------------------------------------------------------------
__global__ __launch_bounds__(NTHR, 2)
void fused_kernel(const float* __restrict__ query, const float* __restrict__ key,
                  const float* __restrict__ value, const float* __restrict__ mask,
                  const float* __restrict__ Wq, const float* __restrict__ bq,
                  const float* __restrict__ Wk, const float* __restrict__ bk,
                  const float* __restrict__ Wv, const float* __restrict__ bv,
                  const float* __restrict__ Wo, const float* __restrict__ bo,
                  const float* __restrict__ gamma, const float* __restrict__ beta,
                  float* __restrict__ out, float* __restrict__ attn_out) {
    extern __shared__ float smem[];
    const int tid  = threadIdx.x;
    const int warp = tid >> 5, lane = tid & 31;

    // ---- Phase 0: convert inputs + weights to fp16 ----
    for (int i = blockIdx.x * NTHR + tid; i < 3 * 1572864; i += NBLK * NTHR) {
        int which = i / 1572864, idx = i - which * 1572864;
        const float* X = (which == 0) ? query : (which == 1) ? key : value;
        float4 w = ((const float4*)X)[idx];
        uint2 u = {hf2(w.x, w.y), hf2(w.z, w.w)};
        ((uint2*)(g_in16 + (size_t)which * BSD))[idx] = u;
    }
    for (int i = blockIdx.x * NTHR + tid; i < 4 * 147456; i += NBLK * NTHR) {
        int which = i / 147456, idx = i - which * 147456;
        const float* Wp = (which == 0) ? Wq : (which == 1) ? Wk
                        : (which == 2) ? Wv : Wo;
        float4 w = ((const float4*)Wp)[idx];
        uint2 u = {hf2(w.x, w.y), hf2(w.z, w.w)};
        ((uint2*)(g_w16 + (size_t)which * WSZ))[idx] = u;
    }
    grid_barrier();

    // ---- Phase 1: QKV projections (1152 jobs, fp16) ----
    for (int job = blockIdx.x; job < 3 * 384; job += NBLK) {
        int which = job / 384;
        int t = job % 384;
        const __half* A16 = g_in16 + (size_t)which * BSD;
        const __half* W16 = g_w16 + (size_t)which * WSZ;
        const float* bb = (which == 0) ? bq : (which == 1) ? bk : bv;
        __half* O16 = (which == 0) ? g_q16 : (which == 1) ? g_k16 : g_v16;
        qkv16_tile(A16, W16, bb, O16, t, smem);
    }
    grid_barrier();

    // ---- Phase 2: sum pass (768 jobs, fp16) ----
    for (int job = blockIdx.x; job < 768; job += NBLK)
        sum_pass(job, mask, smem);
    grid_barrier();

    // ---- Phase 3: ctx + probs pass (768 jobs, fp16) ----
    for (int job = blockIdx.x; job < 768; job += NBLK)
        ctx_probs_pass(job, mask, attn_out, smem);
    grid_barrier();

    // ---- Phase 4: output projection (768 jobs, fp16) ----
    for (int t = blockIdx.x; t < 768; t += NBLK)
        oproj_tile(bo, t, smem);
    grid_barrier();

    // ---- Phase 5: residual + LayerNorm — warp per row ----
    for (int row = blockIdx.x * 16 + warp; row < MROWS; row += NBLK * 16) {
        const float* pp = g_proj + (size_t)row * 768;
        const float* op = query + (size_t)row * 768;

        float4 x[6];
        float sum = 0.0f;
        #pragma unroll
        for (int v = 0; v < 6; v++) {
            int off = v * 128 + lane * 4;
            float4 a = *(const float4*)&pp[off];
            float4 o = *(const float4*)&op[off];
            x[v].x = a.x + o.x; x[v].y = a.y + o.y;
            x[v].z = a.z + o.z; x[v].w = a.w + o.w;
            sum += x[v].x + x[v].y + x[v].z + x[v].w;
        }
        #pragma unroll
        for (int o = 16; o > 0; o >>= 1)
            sum += __shfl_xor_sync(0xFFFFFFFFu, sum, o);
        const float mu = sum * (1.0f / 768.0f);

        float var = 0.0f;
        #pragma unroll
        for (int v = 0; v < 6; v++) {
            float dx = x[v].x - mu, dy = x[v].y - mu;
            float dz = x[v].z - mu, dw = x[v].w - mu;
            var += dx * dx + dy * dy + dz * dz + dw * dw;
        }
        #pragma unroll
        for (int o = 16; o > 0; o >>= 1)
            var += __shfl_xor_sync(0xFFFFFFFFu, var, o);
        const float inv = rsqrtf(var * (1.0f / 768.0f) + 1e-8f);

        #pragma unroll
        for (int v = 0; v < 6; v++) {
            int off = v * 128 + lane * 4;
            float4 g = *(const float4*)&gamma[off];
            float4 bt = *(const float4*)&beta[off];
            float4 r;
            r.x = (x[v].x - mu) * inv * g.x + bt.x;
            r.y = (x[v].y - mu) * inv * g.y + bt.y;
            r.z = (x[v].z - mu) * inv * g.z + bt.z;
            r.w = (x[v].w - mu) * inv * g.w + bt.w;
            *(float4*)&out[(size_t)row * 768 + off] = r;
        }
    }
}

// ---------------------------------------------------------------------------
// Launch
// ---------------------------------------------------------------------------
extern "C" void kernel_launch(void* const* d_in, const int* in_sizes, int n_in,
                              void* d_out, int out_size) {
    const float* big[3]  = {0, 0, 0};
    const float* mats[4] = {0, 0, 0, 0};
    const float* vecs[6] = {0, 0, 0, 0, 0, 0};
    const float* mask = 0;
    int nb = 0, nm = 0, nv = 0;
    for (int i = 0; i < n_in; i++) {
        const float* p = (const float*)d_in[i];
        switch (in_sizes[i]) {
            case 6291456: if (nb < 3) big[nb++] = p;  break;
            case 589824:  if (nm < 4) mats[nm++] = p; break;
            case 768:     if (nv < 6) vecs[nv++] = p; break;
            case 8192:    mask = p;                   break;
            default: break;
        }
    }
    float* out = (float*)d_out;
    float* attn_out = ((long long)out_size >= (long long)BSD + BHSS)
                          ? (out + BSD) : 0;

    cudaFuncSetAttribute(fused_kernel,
                         cudaFuncAttributeMaxDynamicSharedMemorySize, DYN_SMEM);

    fused_kernel<<<NBLK, NTHR, DYN_SMEM>>>(big[0], big[1], big[2], mask,
                                           mats[0], vecs[0], mats[1], vecs[1],
                                           mats[2], vecs[2], mats[3], vecs[3],
                                           vecs[4], vecs[5], out, attn_out);
}